// round 9
// baseline (speedup 1.0000x reference)
#include <cuda_runtime.h>

#define BB 128
typedef unsigned long long u64;

__device__ __forceinline__ u64 pack2(float x, float y){
    u64 r; asm("mov.b64 %0,{%1,%2};" : "=l"(r) : "f"(x), "f"(y)); return r;
}
__device__ __forceinline__ void unpack2(u64 a, float& x, float& y){
    asm("mov.b64 {%0,%1},%2;" : "=f"(x), "=f"(y) : "l"(a));
}
__device__ __forceinline__ u64 fma2(u64 a, u64 b, u64 c){
    u64 d; asm("fma.rn.f32x2 %0,%1,%2,%3;" : "=l"(d) : "l"(a), "l"(b), "l"(c)); return d;
}
__device__ __forceinline__ float fast_tanh(float x){
    float e = __expf(2.0f * x);
    return 1.0f - __fdividef(2.0f, e + 1.0f);
}

#define ST_T16 20
#define ST_T32 36
#define ST_RM  132
#define ST_PX  66

// qkq hosts kkT | qqT | qoT (each 128*ST_T16 = 2560 floats)
// pbuf2 hosts kh1 partials kkT2|qqT2|qoT2|koT2; later aliased by P/X/u/v/P2/X2/v2
#define QKQ_KK 0
#define QKQ_QQ 2560
#define QKQ_QO 5120
#define PB_KK  0
#define PB_QQ  2560
#define PB_QO  5120
#define PB_KO  7680
// union offsets (floats) within pbuf2 (total 12288 floats available)
#define U_P   0        // 16*66 = 1056
#define U_X   1056     // 32*66 = 2112
#define U_U   3168     // 1056
#define U_V   4224     // 1056
#define U_P2  5280     // 1056
#define U_X2  6336     // 2112
#define U_V2  8448     // 1056

struct Smem {
    float sT    [128 * ST_T16];  // states^T
    float oaoT  [136 * ST_T32];  // [states_o | actions_o]^T
    float act   [16 * 8];
    float pol   [16 * 8];
    float qkq   [3 * 128 * ST_T16];   // kkT | qqT | qoT (kh0, then combined)
    float pbuf2 [12288];              // kh1 partials, later P/X/u/v/P2/X2/v2
    float koT   [128 * ST_T32];
    float avoT  [128 * ST_T32];       // raw partial kh0, then tanh(combined)
    float avoT2 [128 * ST_T32];       // raw partial kh1
    float t     [16 * ST_RM];         // s@Wv[:128] kh0
    float t1    [16 * ST_RM];         // kh1
    float avactT[128 * ST_T16];
    float deltaT[128 * ST_T16];
    float w     [256];
    float wo    [512];
    float w2v   [64];
};

__global__ __launch_bounds__(1024, 1)
void critic_kernel(const float* __restrict__ states,
                   const float* __restrict__ policies,
                   const float* __restrict__ actions,
                   const float* __restrict__ states_o,
                   const float* __restrict__ actions_o,
                   const float* __restrict__ Wk,  const float* __restrict__ Wq,
                   const float* __restrict__ Wv,  const float* __restrict__ Wko,
                   const float* __restrict__ Wqo, const float* __restrict__ Wvo,
                   const float* __restrict__ W1,  const float* __restrict__ W2,
                   float* __restrict__ out_value,
                   float* __restrict__ out_w,
                   float* __restrict__ out_wo)
{
    extern __shared__ unsigned char smem_raw[];
    Smem& sm = *reinterpret_cast<Smem*>(smem_raw);

    const int b    = blockIdx.x;
    const int tid  = threadIdx.x;
    const int warp = tid >> 5;
    const int lane = tid & 31;

    // ---------- Stage-1 config: role = warp>>1, kh = warp&1 (k-split) ----------
    const int role = warp >> 1;
    const int kh   = warp & 1;
    int mat, r0, kbeg, kend, koff, astride, col;
    const float* Wm;
    const float* Abase;
    if (role < 8) {
        mat = role >> 1;                       // 0..3 : Wk,Wq,Wqo,Wv
        r0 = 0; astride = ST_T16;
        col = (role & 1) * 64 + lane * 2;
        kbeg = kh * 64; kend = kbeg + 64;
        Wm  = (mat == 0 ? Wk : mat == 1 ? Wq : mat == 2 ? Wqo : Wv) + col;
        Abase = sm.sT;
    } else {
        const int wrp = role - 8;              // 0..7
        mat = 4 + (wrp >> 2);                  // 4: Wko, 5: Wvo
        r0 = ((wrp >> 1) & 1) * 16; astride = ST_T32;
        col = (wrp & 1) * 64 + lane * 2;
        if (mat == 5) { kbeg = kh * 68; kend = kbeg + 68; }
        else          { kbeg = kh * 64; kend = kbeg + 64; }
        Wm  = (mat == 5 ? Wvo : Wko) + col;
        Abase = sm.oaoT;
    }
    koff = kbeg + ((warp * 8) & 63);
    auto ldw = [&](int k){ return *reinterpret_cast<const float2*>(Wm + k * 128); };

    // ---------- Stage 0: load + transpose inputs (1024 threads) ----------
    {
        const int k  = tid & 127;
        const int g  = tid >> 7;       // 0..7
        const float* S = states + (size_t)b * 16 * 128;
        {
            const int rr = g * 2;
            float a0 = S[(rr + 0) * 128 + k];
            float a1 = S[(rr + 1) * 128 + k];
            *reinterpret_cast<float2*>(&sm.sT[k * ST_T16 + rr]) = make_float2(a0, a1);
        }
        const float* SO = states_o + (size_t)b * 32 * 128;
        {
            const int rr = g * 4;
            float a0 = SO[(rr + 0) * 128 + k];
            float a1 = SO[(rr + 1) * 128 + k];
            float a2 = SO[(rr + 2) * 128 + k];
            float a3 = SO[(rr + 3) * 128 + k];
            *reinterpret_cast<float4*>(&sm.oaoT[k * ST_T32 + rr]) = make_float4(a0, a1, a2, a3);
        }
        if (tid < 256) {
            int kk8 = tid >> 5, m = tid & 31;
            sm.oaoT[(128 + kk8) * ST_T32 + m] = actions_o[(size_t)b * 32 * 8 + m * 8 + kk8];
        }
        if (tid < 128) {
            int r = tid >> 3, c = tid & 7;
            sm.act[r * 8 + c] = actions[(size_t)b * 16 * 8 + r * 8 + c];
            sm.pol[r * 8 + c] = policies[(size_t)b * 16 * 8 + r * 8 + c];
        }
        if (tid < 64) sm.w2v[tid] = W2[tid];
    }

    // Prefetch first weight group BEFORE the barrier
    float2 wA = ldw(koff + 0), wB = ldw(koff + 1), wC = ldw(koff + 2), wD = ldw(koff + 3);

    __syncthreads();

    // ---------- Stage 1: projection GEMMs, k-split partials ----------
    {
        u64 acc[2][8];
#pragma unroll
        for (int j = 0; j < 2; j++)
#pragma unroll
            for (int p = 0; p < 8; p++) acc[j][p] = 0ull;

        auto step = [&](int k, float2 w2) {
            const float* Ak = Abase + k * astride + r0;
            const ulonglong2 A0 = *reinterpret_cast<const ulonglong2*>(Ak);
            const ulonglong2 A1 = *reinterpret_cast<const ulonglong2*>(Ak + 4);
            const ulonglong2 A2 = *reinterpret_cast<const ulonglong2*>(Ak + 8);
            const ulonglong2 A3 = *reinterpret_cast<const ulonglong2*>(Ak + 12);
            const u64 wp0 = pack2(w2.x, w2.x);
            const u64 wp1 = pack2(w2.y, w2.y);
            acc[0][0] = fma2(A0.x, wp0, acc[0][0]);
            acc[0][1] = fma2(A0.y, wp0, acc[0][1]);
            acc[0][2] = fma2(A1.x, wp0, acc[0][2]);
            acc[0][3] = fma2(A1.y, wp0, acc[0][3]);
            acc[0][4] = fma2(A2.x, wp0, acc[0][4]);
            acc[0][5] = fma2(A2.y, wp0, acc[0][5]);
            acc[0][6] = fma2(A3.x, wp0, acc[0][6]);
            acc[0][7] = fma2(A3.y, wp0, acc[0][7]);
            acc[1][0] = fma2(A0.x, wp1, acc[1][0]);
            acc[1][1] = fma2(A0.y, wp1, acc[1][1]);
            acc[1][2] = fma2(A1.x, wp1, acc[1][2]);
            acc[1][3] = fma2(A1.y, wp1, acc[1][3]);
            acc[1][4] = fma2(A2.x, wp1, acc[1][4]);
            acc[1][5] = fma2(A2.y, wp1, acc[1][5]);
            acc[1][6] = fma2(A3.x, wp1, acc[1][6]);
            acc[1][7] = fma2(A3.y, wp1, acc[1][7]);
        };

        step(koff + 0, wA);
        step(koff + 1, wB);
        step(koff + 2, wC);
        step(koff + 3, wD);
#pragma unroll 4
        for (int k = koff + 4; k < kend; k++) step(k, ldw(k));
#pragma unroll 4
        for (int k = kbeg; k < koff; k++) step(k, ldw(k));

        if (mat < 3) {
            float* oT = (kh ? sm.pbuf2 : sm.qkq) + mat * 2560;
#pragma unroll
            for (int j = 0; j < 2; j++) {
                float* d = oT + (col + j) * ST_T16;
                ulonglong2 s0 = {acc[j][0], acc[j][1]};
                ulonglong2 s1 = {acc[j][2], acc[j][3]};
                ulonglong2 s2 = {acc[j][4], acc[j][5]};
                ulonglong2 s3 = {acc[j][6], acc[j][7]};
                *reinterpret_cast<ulonglong2*>(d)      = s0;
                *reinterpret_cast<ulonglong2*>(d + 4)  = s1;
                *reinterpret_cast<ulonglong2*>(d + 8)  = s2;
                *reinterpret_cast<ulonglong2*>(d + 12) = s3;
            }
        } else if (mat == 3) {
            float* dt = kh ? sm.t1 : sm.t;
#pragma unroll
            for (int p = 0; p < 8; p++) {
                float x0, y0, x1, y1;
                unpack2(acc[0][p], x0, y0);
                unpack2(acc[1][p], x1, y1);
                *reinterpret_cast<float2*>(&dt[(2 * p + 0) * ST_RM + col]) = make_float2(x0, x1);
                *reinterpret_cast<float2*>(&dt[(2 * p + 1) * ST_RM + col]) = make_float2(y0, y1);
            }
        } else {
            float* oT = (mat == 4) ? (kh ? sm.pbuf2 + PB_KO : sm.koT)
                                   : (kh ? sm.avoT2 : sm.avoT);
#pragma unroll
            for (int j = 0; j < 2; j++) {
                float* d = oT + (col + j) * ST_T32 + r0;
                ulonglong2 s0 = {acc[j][0], acc[j][1]};
                ulonglong2 s1 = {acc[j][2], acc[j][3]};
                ulonglong2 s2 = {acc[j][4], acc[j][5]};
                ulonglong2 s3 = {acc[j][6], acc[j][7]};
                *reinterpret_cast<ulonglong2*>(d)      = s0;
                *reinterpret_cast<ulonglong2*>(d + 4)  = s1;
                *reinterpret_cast<ulonglong2*>(d + 8)  = s2;
                *reinterpret_cast<ulonglong2*>(d + 12) = s3;
            }
        }
    }
    __syncthreads();

    // ---------- Stage 1.5: combine partials + tanh + avact/delta tails ----------
    {
        // qkq += pbuf2[kk|qq|qo]  (3840 float2)
        float2* dq = reinterpret_cast<float2*>(sm.qkq);
        const float2* sq = reinterpret_cast<const float2*>(sm.pbuf2);
        for (int idx = tid; idx < 3840; idx += 1024) {
            float2 a = dq[idx], c = sq[idx];
            dq[idx] = make_float2(a.x + c.x, a.y + c.y);
        }
        // koT += koT2 (2304 float2)
        float2* dk = reinterpret_cast<float2*>(sm.koT);
        const float2* sk = reinterpret_cast<const float2*>(sm.pbuf2 + PB_KO);
        for (int idx = tid; idx < 2304; idx += 1024) {
            float2 a = dk[idx], c = sk[idx];
            dk[idx] = make_float2(a.x + c.x, a.y + c.y);
        }
        // avoT = tanh(avoT + avoT2) (2304 float2)
        float2* da = reinterpret_cast<float2*>(sm.avoT);
        const float2* sa = reinterpret_cast<const float2*>(sm.avoT2);
        for (int idx = tid; idx < 2304; idx += 1024) {
            float2 a = da[idx], c = sa[idx];
            da[idx] = make_float2(fast_tanh(a.x + c.x), fast_tanh(a.y + c.y));
        }
        // tails: avactT / deltaT (2 rows per thread)
        const int g  = tid >> 7;     // 0..7
        const int c  = tid & 127;
        const int rr = g * 2;
        float aa[2], ap[2];
#pragma unroll
        for (int i = 0; i < 2; i++) {
            float tv = sm.t[(rr + i) * ST_RM + c] + sm.t1[(rr + i) * ST_RM + c];
            aa[i] = tv; ap[i] = tv;
        }
#pragma unroll
        for (int k = 0; k < 8; k++) {
            float wv = Wv[(128 + k) * 128 + c];
#pragma unroll
            for (int i = 0; i < 2; i++) {
                aa[i] = fmaf(sm.act[(rr + i) * 8 + k], wv, aa[i]);
                ap[i] = fmaf(sm.pol[(rr + i) * 8 + k], wv, ap[i]);
            }
        }
        float ta0 = fast_tanh(aa[0]);
        float ta1 = fast_tanh(aa[1]);
        float dl0 = fast_tanh(ap[0]) - ta0;
        float dl1 = fast_tanh(ap[1]) - ta1;
        *reinterpret_cast<float2*>(&sm.avactT[c * ST_T16 + rr]) = make_float2(ta0, ta1);
        *reinterpret_cast<float2*>(&sm.deltaT[c * ST_T16 + rr]) = make_float2(dl0, dl1);
    }
    __syncthreads();

    // ---------- Stage 2: attention scores ----------
    const float scale = 0.08838834764831845f;  // 1/sqrt(128)
    if (tid < 128) {
        const int i = tid >> 3, j2 = tid & 7;
        const float* qqT = sm.qkq + QKQ_QQ;
        const float* kkT = sm.qkq + QKQ_KK;
        u64 a0 = 0ull, a1 = 0ull;
#pragma unroll 4
        for (int k = 0; k < 128; k += 2) {
            const float q0 = qqT[(k + 0) * ST_T16 + i];
            const float q1 = qqT[(k + 1) * ST_T16 + i];
            const u64 kp0 = *reinterpret_cast<const u64*>(&kkT[(k + 0) * ST_T16 + 2 * j2]);
            const u64 kp1 = *reinterpret_cast<const u64*>(&kkT[(k + 1) * ST_T16 + 2 * j2]);
            a0 = fma2(pack2(q0, q0), kp0, a0);
            a1 = fma2(pack2(q1, q1), kp1, a1);
        }
        float s0, s1, t0, t1;
        unpack2(a0, s0, s1);
        unpack2(a1, t0, t1);
        *reinterpret_cast<float2*>(&sm.w[i * 16 + 2 * j2]) =
            make_float2((s0 + t0) * scale, (s1 + t1) * scale);
    } else if (tid < 384) {
        const int t2 = tid - 128;
        const int i = t2 >> 4, m2 = t2 & 15;
        const float* qoT = sm.qkq + QKQ_QO;
        u64 a0 = 0ull, a1 = 0ull;
#pragma unroll 4
        for (int k = 0; k < 128; k += 2) {
            const float q0 = qoT[(k + 0) * ST_T16 + i];
            const float q1 = qoT[(k + 1) * ST_T16 + i];
            const u64 kp0 = *reinterpret_cast<const u64*>(&sm.koT[(k + 0) * ST_T32 + 2 * m2]);
            const u64 kp1 = *reinterpret_cast<const u64*>(&sm.koT[(k + 1) * ST_T32 + 2 * m2]);
            a0 = fma2(pack2(q0, q0), kp0, a0);
            a1 = fma2(pack2(q1, q1), kp1, a1);
        }
        float s0, s1, t0, t1;
        unpack2(a0, s0, s1);
        unpack2(a1, t0, t1);
        *reinterpret_cast<float2*>(&sm.wo[i * 32 + 2 * m2]) =
            make_float2((s0 + t0) * scale, (s1 + t1) * scale);
    }

    // ---------- Stage-3 config + prefetch (before barrier), k-split by thread half ----------
    const int half = tid >> 9;        // 0 or 1 : k-half
    const int tid2 = tid & 511;
    const float* AT;
    const float* Wg;
    float* dst3;
    int r03, strideA3, col3;
    if (tid2 < 256) {
        const int cq2 = tid2 & 31;
        const int rg  = tid2 >> 5;
        col3 = cq2 * 2;
        AT   = (rg < 4 ? sm.avactT : sm.deltaT);
        r03  = (rg & 3) * 4;
        strideA3 = ST_T16;
        Wg   = W1;
        dst3 = sm.pbuf2 + (rg < 4 ? (half ? U_P2 : U_P) : (half ? U_V2 : U_V));
    } else {
        const int tid3 = tid2 - 256;
        const int cq2 = tid3 & 31;
        const int rg  = tid3 >> 5;
        col3 = cq2 * 2;
        AT   = sm.avoT;
        r03  = rg * 4;
        strideA3 = ST_T32;
        Wg   = W1 + 128 * 64;
        dst3 = sm.pbuf2 + (half ? U_X2 : U_X);
    }
    const int kbeg3 = half * 64;
    const int kend3 = kbeg3 + 64;
    const int koff3 = kbeg3 + ((tid2 >> 5) & 7) * 8;
    auto ldw3 = [&](int k){ return *reinterpret_cast<const float2*>(Wg + k * 64 + col3); };
    float2 pA = ldw3(koff3 + 0), pB = ldw3(koff3 + 1), pC = ldw3(koff3 + 2), pD = ldw3(koff3 + 3);

    __syncthreads();

    // ---------- Stage 3: softmaxes + P/v/X half-GEMMs ----------
    if (tid < 16) {
        const int i = tid;
        float mx = -1e30f;
#pragma unroll
        for (int j = 0; j < 16; j++) mx = fmaxf(mx, sm.w[i * 16 + j]);
        float s = 0.f, e[16];
#pragma unroll
        for (int j = 0; j < 16; j++) { e[j] = __expf(sm.w[i * 16 + j] - mx); s += e[j]; }
        const float inv = __fdividef(1.f, s);
#pragma unroll
        for (int j = 0; j < 16; j++) {
            float p = e[j] * inv;
            sm.w[i * 16 + j] = p;
            out_w[(size_t)b * 256 + i * 16 + j] = p;
        }
    } else if (tid < 48) {
        const int m = tid - 16;
        float mx = -1e30f;
#pragma unroll
        for (int i = 0; i < 16; i++) mx = fmaxf(mx, sm.wo[i * 32 + m]);
        float s = 0.f, e[16];
#pragma unroll
        for (int i = 0; i < 16; i++) { e[i] = __expf(sm.wo[i * 32 + m] - mx); s += e[i]; }
        const float inv = __fdividef(1.f, s);
#pragma unroll
        for (int i = 0; i < 16; i++) {
            float p = e[i] * inv;
            sm.wo[i * 32 + m] = p;
            out_wo[(size_t)b * 512 + i * 32 + m] = p;
        }
    }
    {
        u64 a00 = 0ull, a01 = 0ull, a10 = 0ull, a11 = 0ull;
        auto step3 = [&](int k, float2 wv) {
            const ulonglong2 A = *reinterpret_cast<const ulonglong2*>(&AT[k * strideA3 + r03]);
            const u64 wp0 = pack2(wv.x, wv.x);
            const u64 wp1 = pack2(wv.y, wv.y);
            a00 = fma2(A.x, wp0, a00);
            a01 = fma2(A.y, wp0, a01);
            a10 = fma2(A.x, wp1, a10);
            a11 = fma2(A.y, wp1, a11);
        };
        step3(koff3 + 0, pA);
        step3(koff3 + 1, pB);
        step3(koff3 + 2, pC);
        step3(koff3 + 3, pD);
#pragma unroll 4
        for (int k = koff3 + 4; k < kend3; k++) step3(k, ldw3(k));
#pragma unroll 4
        for (int k = kbeg3; k < koff3; k++) step3(k, ldw3(k));

        float x0, x1, x2, x3, y0, y1, y2, y3;
        unpack2(a00, x0, x1); unpack2(a01, x2, x3);
        unpack2(a10, y0, y1); unpack2(a11, y2, y3);
        *reinterpret_cast<float2*>(&dst3[(r03 + 0) * ST_PX + col3]) = make_float2(x0, y0);
        *reinterpret_cast<float2*>(&dst3[(r03 + 1) * ST_PX + col3]) = make_float2(x1, y1);
        *reinterpret_cast<float2*>(&dst3[(r03 + 2) * ST_PX + col3]) = make_float2(x2, y2);
        *reinterpret_cast<float2*>(&dst3[(r03 + 3) * ST_PX + col3]) = make_float2(x3, y3);
    }
    __syncthreads();

    // ---------- Stage 5: u = w @ (P+P2) + wo @ (X+X2)  (1024 threads, 1 col each) ----------
    {
        const int i = tid >> 6;          // 0..15
        const int c = tid & 63;
        const float* Pp  = sm.pbuf2 + U_P;
        const float* P2p = sm.pbuf2 + U_P2;
        const float* Xp  = sm.pbuf2 + U_X;
        const float* X2p = sm.pbuf2 + U_X2;
        float acc0 = 0.f, acc1 = 0.f;
#pragma unroll
        for (int j = 0; j < 16; j += 2) {
            acc0 = fmaf(sm.w[i * 16 + j],     Pp[j * ST_PX + c] + P2p[j * ST_PX + c],         acc0);
            acc1 = fmaf(sm.w[i * 16 + j + 1], Pp[(j + 1) * ST_PX + c] + P2p[(j + 1) * ST_PX + c], acc1);
        }
#pragma unroll
        for (int m = 0; m < 32; m += 2) {
            acc0 = fmaf(sm.wo[i * 32 + m],     Xp[m * ST_PX + c] + X2p[m * ST_PX + c],         acc0);
            acc1 = fmaf(sm.wo[i * 32 + m + 1], Xp[(m + 1) * ST_PX + c] + X2p[(m + 1) * ST_PX + c], acc1);
        }
        sm.pbuf2[U_U + i * ST_PX + c] = acc0 + acc1;
    }
    __syncthreads();

    // ---------- Stage 6: final value (4 threads per (i,j) pair) ----------
    {
        const int p = tid >> 2, h = tid & 3;
        const int i = p >> 4, j = p & 15;
        const float wt = sm.w[i * 16 + j];
        const float* up  = sm.pbuf2 + U_U;
        const float* vp  = sm.pbuf2 + U_V;
        const float* v2p = sm.pbuf2 + U_V2;
        float acc0 = 0.f, acc1 = 0.f;
        const int d0 = h * 16;
#pragma unroll
        for (int d = d0; d < d0 + 16; d += 2) {
            float vv0 = vp[j * ST_PX + d]     + v2p[j * ST_PX + d];
            float vv1 = vp[j * ST_PX + d + 1] + v2p[j * ST_PX + d + 1];
            float h0 = fmaf(wt, vv0, up[i * ST_PX + d]);
            float h1 = fmaf(wt, vv1, up[i * ST_PX + d + 1]);
            h0 = fmaxf(h0, 0.01f * h0);
            h1 = fmaxf(h1, 0.01f * h1);
            acc0 = fmaf(h0, sm.w2v[d],     acc0);
            acc1 = fmaf(h1, sm.w2v[d + 1], acc1);
        }
        float acc = acc0 + acc1;
        acc += __shfl_xor_sync(0xffffffffu, acc, 1);
        acc += __shfl_xor_sync(0xffffffffu, acc, 2);
        if (h == 0) out_value[(size_t)b * 256 + p] = acc;
    }
}

extern "C" void kernel_launch(void* const* d_in, const int* in_sizes, int n_in,
                              void* d_out, int out_size) {
    const float* states    = (const float*)d_in[0];
    const float* policies  = (const float*)d_in[1];
    const float* actions   = (const float*)d_in[2];
    const float* states_o  = (const float*)d_in[3];
    const float* actions_o = (const float*)d_in[4];
    const float* Wk  = (const float*)d_in[5];
    const float* Wq  = (const float*)d_in[6];
    const float* Wv  = (const float*)d_in[7];
    const float* Wko = (const float*)d_in[8];
    const float* Wqo = (const float*)d_in[9];
    const float* Wvo = (const float*)d_in[10];
    const float* W1  = (const float*)d_in[11];
    const float* W2  = (const float*)d_in[12];

    float* out       = (float*)d_out;
    float* out_value = out;                    // [B,N,N,1]
    float* out_w     = out + BB * 256;         // [B,N,N]
    float* out_wo    = out + 2 * BB * 256;     // [B,N,M,1]

    cudaFuncSetAttribute(critic_kernel,
                         cudaFuncAttributeMaxDynamicSharedMemorySize,
                         (int)sizeof(Smem));

    critic_kernel<<<BB, 1024, sizeof(Smem)>>>(states, policies, actions,
                                              states_o, actions_o,
                                              Wk, Wq, Wv, Wko, Wqo, Wvo, W1, W2,
                                              out_value, out_w, out_wo);
}

// round 10
// speedup vs baseline: 1.1333x; 1.1333x over previous
#include <cuda_runtime.h>

#define BB 128
typedef unsigned long long u64;

__device__ __forceinline__ u64 pack2(float x, float y){
    u64 r; asm("mov.b64 %0,{%1,%2};" : "=l"(r) : "f"(x), "f"(y)); return r;
}
__device__ __forceinline__ void unpack2(u64 a, float& x, float& y){
    asm("mov.b64 {%0,%1},%2;" : "=f"(x), "=f"(y) : "l"(a));
}
__device__ __forceinline__ u64 fma2(u64 a, u64 b, u64 c){
    u64 d; asm("fma.rn.f32x2 %0,%1,%2,%3;" : "=l"(d) : "l"(a), "l"(b), "l"(c)); return d;
}
__device__ __forceinline__ float fast_tanh(float x){
    float e = __expf(2.0f * x);
    return 1.0f - __fdividef(2.0f, e + 1.0f);
}

// Folded score matrices (recomputed every launch -> deterministic)
__device__ float Gd [128 * 128];   // G [d][d'] = dot(Wq_row_d , Wk_row_d')
__device__ float God[128 * 128];   // Go[d][e ] = dot(Wqo_row_d, Wko_row_e)

// ============ Precompute kernel (verified in R7) ============
__global__ __launch_bounds__(256, 1)
void gg_kernel(const float* __restrict__ Wq,  const float* __restrict__ Wk,
               const float* __restrict__ Wqo, const float* __restrict__ Wko)
{
    __shared__ float aT[128 * 18];   // aT[a][r], 16 rows
    __shared__ float bT[128 * 66];   // bT[a][e], 64 e-cols
    const int tid = threadIdx.x;
    const int cta = blockIdx.x;          // 0..31
    const bool second = cta >= 16;
    const int c  = cta & 15;
    const int d0 = (c >> 1) * 16;
    const int e0 = (c & 1) * 64;
    const float* Wa = second ? Wqo : Wq;
    const float* Wb = second ? Wko : Wk;
    float* Gout = second ? God : Gd;

    for (int idx = tid; idx < 16 * 128; idx += 256) {
        int r = idx >> 7, a = idx & 127;
        aT[a * 18 + r] = Wa[(d0 + r) * 128 + a];
    }
    for (int idx = tid; idx < 64 * 128; idx += 256) {
        int e = idx >> 7, a = idx & 127;
        bT[a * 66 + e] = Wb[(e0 + e) * 128 + a];
    }
    __syncthreads();

    const int e2 = tid & 31;
    const int rg = tid >> 5;
    u64 acc0 = 0ull, acc1 = 0ull;
#pragma unroll 4
    for (int a = 0; a < 128; a++) {
        const u64 we = *reinterpret_cast<const u64*>(&bT[a * 66 + 2 * e2]);
        const float2 ar = *reinterpret_cast<const float2*>(&aT[a * 18 + 2 * rg]);
        acc0 = fma2(pack2(ar.x, ar.x), we, acc0);
        acc1 = fma2(pack2(ar.y, ar.y), we, acc1);
    }
    float x0, x1, y0, y1;
    unpack2(acc0, x0, x1);
    unpack2(acc1, y0, y1);
    float* g0 = Gout + (d0 + 2 * rg) * 128 + e0 + 2 * e2;
    *reinterpret_cast<float2*>(g0)       = make_float2(x0, x1);
    *reinterpret_cast<float2*>(g0 + 128) = make_float2(y0, y1);
}

#define ST_T16 20
#define ST_T32 36
#define ST_RM  132
#define ST_PX  66

struct Smem {
    float sT    [128 * ST_T16];  // states^T
    float oaoT  [136 * ST_T32];  // [states_o | actions_o]^T
    float act   [16 * 8];
    float pol   [16 * 8];
    float YT    [128 * ST_T16];  // (s@G)^T
    float YoT   [128 * ST_T16];  // (s@Go)^T
    float t     [16 * ST_RM];    // s@Wv[:128] k-half 0
    float t1    [16 * ST_RM];    //             k-half 1
    float avoT  [128 * ST_T32];  // tanh(oao @ Wvo), transposed
    float avactT[128 * ST_T16];
    float deltaT[128 * ST_T16];
    float w     [256];
    float wo    [512];
    float P     [16 * ST_PX];
    float X     [32 * ST_PX];
    float u     [16 * ST_PX];
    float v     [16 * ST_PX];
    float w2v   [64];
};

__global__ __launch_bounds__(512, 1)
void critic_kernel(const float* __restrict__ states,
                   const float* __restrict__ policies,
                   const float* __restrict__ actions,
                   const float* __restrict__ states_o,
                   const float* __restrict__ actions_o,
                   const float* __restrict__ Wv,
                   const float* __restrict__ Wvo,
                   const float* __restrict__ W1,  const float* __restrict__ W2,
                   float* __restrict__ out_value,
                   float* __restrict__ out_w,
                   float* __restrict__ out_wo)
{
    extern __shared__ unsigned char smem_raw[];
    Smem& sm = *reinterpret_cast<Smem*>(smem_raw);

    const int b    = blockIdx.x;
    const int tid  = threadIdx.x;
    const int warp = tid >> 5;
    const int lane = tid & 31;

    // ---------- Stage-1 config ----------
    // warps 0-3 : G/Go (16 rows, full k).  mat = warp>>1 (0:G, 1:Go), col-half = warp&1
    // warps 4-7 : Wv (16 rows, k-split).   sub = warp-4: kh = sub>>1, col-half = sub&1
    // warps 8-15: Wvo (8 rows, full 136k). wrp = warp-8: r0 = (wrp>>1)*8, col-half = wrp&1
    int r0 = 0, kbeg, kend, koff, col;
    const float* Wm;
    int cls;  // 0: G/Go, 1: Wv, 2: Wvo
    if (warp < 4) {
        cls = 0;
        col = (warp & 1) * 64 + lane * 2;
        kbeg = 0; kend = 128;
        koff = warp * 32;
        Wm = ((warp >> 1) == 0 ? Gd : God) + col;
    } else if (warp < 8) {
        cls = 1;
        const int sub = warp - 4;
        col = (sub & 1) * 64 + lane * 2;
        const int kh = sub >> 1;
        kbeg = kh * 64; kend = kbeg + 64;
        koff = kbeg + (((sub) * 16 + 8) & 63);
        Wm = Wv + col;
    } else {
        cls = 2;
        const int wrp = warp - 8;
        r0 = (wrp >> 1) * 8;
        col = (wrp & 1) * 64 + lane * 2;
        kbeg = 0; kend = 136;
        koff = (wrp * 16 + 4) & 127;
        Wm = Wvo + col;
    }
    auto ldw = [&](int k){ return *reinterpret_cast<const float2*>(Wm + k * 128); };

    // ---------- Stage 0: load + transpose inputs ----------
    {
        const int k  = tid & 127;
        const int g  = tid >> 7;       // 0..3
        const int rr = g * 4;
        const float* S = states + (size_t)b * 16 * 128;
        {
            float a0 = S[(rr + 0) * 128 + k];
            float a1 = S[(rr + 1) * 128 + k];
            float a2 = S[(rr + 2) * 128 + k];
            float a3 = S[(rr + 3) * 128 + k];
            *reinterpret_cast<float4*>(&sm.sT[k * ST_T16 + rr]) = make_float4(a0, a1, a2, a3);
        }
        const float* SO = states_o + (size_t)b * 32 * 128;
#pragma unroll
        for (int h = 0; h < 32; h += 16) {
            float a0 = SO[(rr + h + 0) * 128 + k];
            float a1 = SO[(rr + h + 1) * 128 + k];
            float a2 = SO[(rr + h + 2) * 128 + k];
            float a3 = SO[(rr + h + 3) * 128 + k];
            *reinterpret_cast<float4*>(&sm.oaoT[k * ST_T32 + rr + h]) = make_float4(a0, a1, a2, a3);
        }
        if (tid < 256) {
            int kk8 = tid >> 5, m = tid & 31;
            sm.oaoT[(128 + kk8) * ST_T32 + m] = actions_o[(size_t)b * 32 * 8 + m * 8 + kk8];
        }
        if (tid < 128) {
            int r = tid >> 3, c = tid & 7;
            sm.act[r * 8 + c] = actions[(size_t)b * 16 * 8 + r * 8 + c];
            sm.pol[r * 8 + c] = policies[(size_t)b * 16 * 8 + r * 8 + c];
        }
        if (tid < 64) sm.w2v[tid] = W2[tid];
    }

    // Deep prefetch (8 k-steps) BEFORE the barrier
    float2 wA = ldw(koff + 0), wB = ldw(koff + 1), wC = ldw(koff + 2), wD = ldw(koff + 3);
    float2 wE = ldw(koff + 4), wF = ldw(koff + 5), wG = ldw(koff + 6), wH = ldw(koff + 7);

    __syncthreads();

    // ---------- Stage 1 ----------
    if (cls < 2) {
        // 16-row GEMMs (G / Go / Wv)
        u64 acc[2][8];
#pragma unroll
        for (int j = 0; j < 2; j++)
#pragma unroll
            for (int p = 0; p < 8; p++) acc[j][p] = 0ull;

        auto step = [&](int k, float2 w2) {
            const float* Ak = sm.sT + k * ST_T16;
            const ulonglong2 A0 = *reinterpret_cast<const ulonglong2*>(Ak);
            const ulonglong2 A1 = *reinterpret_cast<const ulonglong2*>(Ak + 4);
            const ulonglong2 A2 = *reinterpret_cast<const ulonglong2*>(Ak + 8);
            const ulonglong2 A3 = *reinterpret_cast<const ulonglong2*>(Ak + 12);
            const u64 wp0 = pack2(w2.x, w2.x);
            const u64 wp1 = pack2(w2.y, w2.y);
            acc[0][0] = fma2(A0.x, wp0, acc[0][0]);
            acc[0][1] = fma2(A0.y, wp0, acc[0][1]);
            acc[0][2] = fma2(A1.x, wp0, acc[0][2]);
            acc[0][3] = fma2(A1.y, wp0, acc[0][3]);
            acc[0][4] = fma2(A2.x, wp0, acc[0][4]);
            acc[0][5] = fma2(A2.y, wp0, acc[0][5]);
            acc[0][6] = fma2(A3.x, wp0, acc[0][6]);
            acc[0][7] = fma2(A3.y, wp0, acc[0][7]);
            acc[1][0] = fma2(A0.x, wp1, acc[1][0]);
            acc[1][1] = fma2(A0.y, wp1, acc[1][1]);
            acc[1][2] = fma2(A1.x, wp1, acc[1][2]);
            acc[1][3] = fma2(A1.y, wp1, acc[1][3]);
            acc[1][4] = fma2(A2.x, wp1, acc[1][4]);
            acc[1][5] = fma2(A2.y, wp1, acc[1][5]);
            acc[1][6] = fma2(A3.x, wp1, acc[1][6]);
            acc[1][7] = fma2(A3.y, wp1, acc[1][7]);
        };

        step(koff + 0, wA);
        step(koff + 1, wB);
        step(koff + 2, wC);
        step(koff + 3, wD);
        step(koff + 4, wE);
        step(koff + 5, wF);
        step(koff + 6, wG);
        step(koff + 7, wH);
#pragma unroll 8
        for (int k = koff + 8; k < kend; k++) step(k, ldw(k));
#pragma unroll 8
        for (int k = kbeg; k < koff; k++) step(k, ldw(k));

        if (cls == 0) {
            float* oT = ((warp >> 1) == 0 ? sm.YT : sm.YoT);
#pragma unroll
            for (int j = 0; j < 2; j++) {
                float* d = oT + (col + j) * ST_T16;
                ulonglong2 s0 = {acc[j][0], acc[j][1]};
                ulonglong2 s1 = {acc[j][2], acc[j][3]};
                ulonglong2 s2 = {acc[j][4], acc[j][5]};
                ulonglong2 s3 = {acc[j][6], acc[j][7]};
                *reinterpret_cast<ulonglong2*>(d)      = s0;
                *reinterpret_cast<ulonglong2*>(d + 4)  = s1;
                *reinterpret_cast<ulonglong2*>(d + 8)  = s2;
                *reinterpret_cast<ulonglong2*>(d + 12) = s3;
            }
        } else {
            float* dt = ((warp - 4) >> 1) ? sm.t1 : sm.t;
#pragma unroll
            for (int p = 0; p < 8; p++) {
                float x0, y0, x1, y1;
                unpack2(acc[0][p], x0, y0);
                unpack2(acc[1][p], x1, y1);
                *reinterpret_cast<float2*>(&dt[(2 * p + 0) * ST_RM + col]) = make_float2(x0, x1);
                *reinterpret_cast<float2*>(&dt[(2 * p + 1) * ST_RM + col]) = make_float2(y0, y1);
            }
        }
    } else {
        // Wvo: 8 rows x 2 cols, 136 k-steps, tanh epilogue
        u64 acc[2][4];
#pragma unroll
        for (int j = 0; j < 2; j++)
#pragma unroll
            for (int p = 0; p < 4; p++) acc[j][p] = 0ull;

        auto stepo = [&](int k, float2 w2) {
            const float* Ak = sm.oaoT + k * ST_T32 + r0;
            const ulonglong2 A0 = *reinterpret_cast<const ulonglong2*>(Ak);
            const ulonglong2 A1 = *reinterpret_cast<const ulonglong2*>(Ak + 4);
            const u64 wp0 = pack2(w2.x, w2.x);
            const u64 wp1 = pack2(w2.y, w2.y);
            acc[0][0] = fma2(A0.x, wp0, acc[0][0]);
            acc[0][1] = fma2(A0.y, wp0, acc[0][1]);
            acc[0][2] = fma2(A1.x, wp0, acc[0][2]);
            acc[0][3] = fma2(A1.y, wp0, acc[0][3]);
            acc[1][0] = fma2(A0.x, wp1, acc[1][0]);
            acc[1][1] = fma2(A0.y, wp1, acc[1][1]);
            acc[1][2] = fma2(A1.x, wp1, acc[1][2]);
            acc[1][3] = fma2(A1.y, wp1, acc[1][3]);
        };

        stepo(koff + 0, wA);
        stepo(koff + 1, wB);
        stepo(koff + 2, wC);
        stepo(koff + 3, wD);
        stepo(koff + 4, wE);
        stepo(koff + 5, wF);
        stepo(koff + 6, wG);
        stepo(koff + 7, wH);
#pragma unroll 8
        for (int k = koff + 8; k < 136; k++) stepo(k, ldw(k));
#pragma unroll 8
        for (int k = 0; k < koff; k++) stepo(k, ldw(k));

#pragma unroll
        for (int j = 0; j < 2; j++) {
            float t0, t1_, t2, t3, t4, t5, t6, t7;
            unpack2(acc[j][0], t0, t1_);
            unpack2(acc[j][1], t2, t3);
            unpack2(acc[j][2], t4, t5);
            unpack2(acc[j][3], t6, t7);
            float* d = sm.avoT + (col + j) * ST_T32 + r0;
            *reinterpret_cast<float4*>(d)     = make_float4(fast_tanh(t0), fast_tanh(t1_), fast_tanh(t2), fast_tanh(t3));
            *reinterpret_cast<float4*>(d + 4) = make_float4(fast_tanh(t4), fast_tanh(t5), fast_tanh(t6), fast_tanh(t7));
        }
    }
    __syncthreads();

    // ---------- Stage 2: avactT/deltaT tails + attention scores ----------
    {
        const int g  = tid >> 7;    // 0..3
        const int c  = tid & 127;
        const int rr = g * 4;
        float aa[4], ap[4];
#pragma unroll
        for (int i = 0; i < 4; i++) {
            float tv = sm.t[(rr + i) * ST_RM + c] + sm.t1[(rr + i) * ST_RM + c];
            aa[i] = tv; ap[i] = tv;
        }
#pragma unroll
        for (int k = 0; k < 8; k++) {
            float wv = Wv[(128 + k) * 128 + c];
#pragma unroll
            for (int i = 0; i < 4; i++) {
                aa[i] = fmaf(sm.act[(rr + i) * 8 + k], wv, aa[i]);
                ap[i] = fmaf(sm.pol[(rr + i) * 8 + k], wv, ap[i]);
            }
        }
        float ta[4], dl[4];
#pragma unroll
        for (int i = 0; i < 4; i++) {
            ta[i] = fast_tanh(aa[i]);
            dl[i] = fast_tanh(ap[i]) - ta[i];
        }
        *reinterpret_cast<float4*>(&sm.avactT[c * ST_T16 + rr]) = make_float4(ta[0], ta[1], ta[2], ta[3]);
        *reinterpret_cast<float4*>(&sm.deltaT[c * ST_T16 + rr]) = make_float4(dl[0], dl[1], dl[2], dl[3]);
    }
    const float scale = 0.08838834764831845f;  // 1/sqrt(128)
    if (tid < 128) {
        // w[i][j] = Y[i] . s[j]
        const int i = tid >> 3, j2 = tid & 7;
        u64 a0 = 0ull, a1 = 0ull;
#pragma unroll 4
        for (int k = 0; k < 128; k += 2) {
            const float q0 = sm.YT[(k + 0) * ST_T16 + i];
            const float q1 = sm.YT[(k + 1) * ST_T16 + i];
            const u64 kp0 = *reinterpret_cast<const u64*>(&sm.sT[(k + 0) * ST_T16 + 2 * j2]);
            const u64 kp1 = *reinterpret_cast<const u64*>(&sm.sT[(k + 1) * ST_T16 + 2 * j2]);
            a0 = fma2(pack2(q0, q0), kp0, a0);
            a1 = fma2(pack2(q1, q1), kp1, a1);
        }
        float s0, s1, t0, t1;
        unpack2(a0, s0, s1);
        unpack2(a1, t0, t1);
        *reinterpret_cast<float2*>(&sm.w[i * 16 + 2 * j2]) =
            make_float2((s0 + t0) * scale, (s1 + t1) * scale);
    } else if (tid < 384) {
        // wo[i][m] = Yo[i] . s_o[m]
        const int t2 = tid - 128;
        const int i = t2 >> 4, m2 = t2 & 15;
        u64 a0 = 0ull, a1 = 0ull;
#pragma unroll 4
        for (int k = 0; k < 128; k += 2) {
            const float q0 = sm.YoT[(k + 0) * ST_T16 + i];
            const float q1 = sm.YoT[(k + 1) * ST_T16 + i];
            const u64 kp0 = *reinterpret_cast<const u64*>(&sm.oaoT[(k + 0) * ST_T32 + 2 * m2]);
            const u64 kp1 = *reinterpret_cast<const u64*>(&sm.oaoT[(k + 1) * ST_T32 + 2 * m2]);
            a0 = fma2(pack2(q0, q0), kp0, a0);
            a1 = fma2(pack2(q1, q1), kp1, a1);
        }
        float s0, s1, t0, t1;
        unpack2(a0, s0, s1);
        unpack2(a1, t0, t1);
        *reinterpret_cast<float2*>(&sm.wo[i * 32 + 2 * m2]) =
            make_float2((s0 + t0) * scale, (s1 + t1) * scale);
    }

    // ---------- Stage-3 config + deep prefetch (before barrier) ----------
    const float* AT;
    const float* Wg;
    float* dst3;
    int r03, strideA3, col3;
    if (tid < 256) {
        const int cq2 = tid & 31;
        const int rg  = tid >> 5;
        col3 = cq2 * 2;
        AT   = (rg < 4 ? sm.avactT : sm.deltaT);
        r03  = (rg & 3) * 4;
        strideA3 = ST_T16;
        Wg   = W1;
        dst3 = (rg < 4 ? sm.P : sm.v);
    } else {
        const int tid2 = tid - 256;
        const int cq2 = tid2 & 31;
        const int rg  = tid2 >> 5;
        col3 = cq2 * 2;
        AT   = sm.avoT;
        r03  = rg * 4;
        strideA3 = ST_T32;
        Wg   = W1 + 128 * 64;
        dst3 = sm.X;
    }
    const int koff3 = ((tid >> 5) & 7) * 16;
    auto ldw3 = [&](int k){ return *reinterpret_cast<const float2*>(Wg + k * 64 + col3); };
    float2 pA = ldw3(koff3 + 0), pB = ldw3(koff3 + 1), pC = ldw3(koff3 + 2), pD = ldw3(koff3 + 3);
    float2 pE = ldw3(koff3 + 4), pF = ldw3(koff3 + 5), pG = ldw3(koff3 + 6), pH = ldw3(koff3 + 7);

    __syncthreads();

    // ---------- Stage 3: softmaxes + P/v/X GEMMs ----------
    if (tid < 16) {
        const int i = tid;
        float mx = -1e30f;
#pragma unroll
        for (int j = 0; j < 16; j++) mx = fmaxf(mx, sm.w[i * 16 + j]);
        float s = 0.f, e[16];
#pragma unroll
        for (int j = 0; j < 16; j++) { e[j] = __expf(sm.w[i * 16 + j] - mx); s += e[j]; }
        const float inv = __fdividef(1.f, s);
#pragma unroll
        for (int j = 0; j < 16; j++) {
            float p = e[j] * inv;
            sm.w[i * 16 + j] = p;
            out_w[(size_t)b * 256 + i * 16 + j] = p;
        }
    } else if (tid < 48) {
        const int m = tid - 16;
        float mx = -1e30f;
#pragma unroll
        for (int i = 0; i < 16; i++) mx = fmaxf(mx, sm.wo[i * 32 + m]);
        float s = 0.f, e[16];
#pragma unroll
        for (int i = 0; i < 16; i++) { e[i] = __expf(sm.wo[i * 32 + m] - mx); s += e[i]; }
        const float inv = __fdividef(1.f, s);
#pragma unroll
        for (int i = 0; i < 16; i++) {
            float p = e[i] * inv;
            sm.wo[i * 32 + m] = p;
            out_wo[(size_t)b * 512 + i * 32 + m] = p;
        }
    }
    {
        u64 a00 = 0ull, a01 = 0ull, a10 = 0ull, a11 = 0ull;
        auto step3 = [&](int k, float2 wv) {
            const ulonglong2 A = *reinterpret_cast<const ulonglong2*>(&AT[k * strideA3 + r03]);
            const u64 wp0 = pack2(wv.x, wv.x);
            const u64 wp1 = pack2(wv.y, wv.y);
            a00 = fma2(A.x, wp0, a00);
            a01 = fma2(A.y, wp0, a01);
            a10 = fma2(A.x, wp1, a10);
            a11 = fma2(A.y, wp1, a11);
        };
        step3(koff3 + 0, pA);
        step3(koff3 + 1, pB);
        step3(koff3 + 2, pC);
        step3(koff3 + 3, pD);
        step3(koff3 + 4, pE);
        step3(koff3 + 5, pF);
        step3(koff3 + 6, pG);
        step3(koff3 + 7, pH);
#pragma unroll 8
        for (int k = koff3 + 8; k < 128; k++) step3(k, ldw3(k));
#pragma unroll 8
        for (int k = 0; k < koff3; k++) step3(k, ldw3(k));

        float x0, x1, x2, x3, y0, y1, y2, y3;
        unpack2(a00, x0, x1); unpack2(a01, x2, x3);
        unpack2(a10, y0, y1); unpack2(a11, y2, y3);
        *reinterpret_cast<float2*>(&dst3[(r03 + 0) * ST_PX + col3]) = make_float2(x0, y0);
        *reinterpret_cast<float2*>(&dst3[(r03 + 1) * ST_PX + col3]) = make_float2(x1, y1);
        *reinterpret_cast<float2*>(&dst3[(r03 + 2) * ST_PX + col3]) = make_float2(x2, y2);
        *reinterpret_cast<float2*>(&dst3[(r03 + 3) * ST_PX + col3]) = make_float2(x3, y3);
    }
    __syncthreads();

    // ---------- Stage 5: u = w @ P + wo @ X ----------
    {
        const int i = tid >> 5;
        const int c = (tid & 31) * 2;
        float acc0 = 0.f, acc1 = 0.f, bcc0 = 0.f, bcc1 = 0.f;
#pragma unroll
        for (int j = 0; j < 16; j += 2) {
            const float wv0 = sm.w[i * 16 + j];
            const float wv1 = sm.w[i * 16 + j + 1];
            const float2 p0 = *reinterpret_cast<const float2*>(&sm.P[j * ST_PX + c]);
            const float2 p1 = *reinterpret_cast<const float2*>(&sm.P[(j + 1) * ST_PX + c]);
            acc0 = fmaf(wv0, p0.x, acc0);
            acc1 = fmaf(wv0, p0.y, acc1);
            bcc0 = fmaf(wv1, p1.x, bcc0);
            bcc1 = fmaf(wv1, p1.y, bcc1);
        }
#pragma unroll
        for (int m = 0; m < 32; m += 2) {
            const float wv0 = sm.wo[i * 32 + m];
            const float wv1 = sm.wo[i * 32 + m + 1];
            const float2 x0 = *reinterpret_cast<const float2*>(&sm.X[m * ST_PX + c]);
            const float2 x1 = *reinterpret_cast<const float2*>(&sm.X[(m + 1) * ST_PX + c]);
            acc0 = fmaf(wv0, x0.x, acc0);
            acc1 = fmaf(wv0, x0.y, acc1);
            bcc0 = fmaf(wv1, x1.x, bcc0);
            bcc1 = fmaf(wv1, x1.y, bcc1);
        }
        *reinterpret_cast<float2*>(&sm.u[i * ST_PX + c]) = make_float2(acc0 + bcc0, acc1 + bcc1);
    }
    __syncthreads();

    // ---------- Stage 6: final value ----------
    {
        const int p = tid >> 1, h = tid & 1;
        const int i = p >> 4, j = p & 15;
        const float wt = sm.w[i * 16 + j];
        float acc0 = 0.f, acc1 = 0.f;
        const int d0 = h * 32;
#pragma unroll
        for (int d = d0; d < d0 + 32; d += 2) {
            float h0 = fmaf(wt, sm.v[j * ST_PX + d],     sm.u[i * ST_PX + d]);
            float h1 = fmaf(wt, sm.v[j * ST_PX + d + 1], sm.u[i * ST_PX + d + 1]);
            h0 = fmaxf(h0, 0.01f * h0);
            h1 = fmaxf(h1, 0.01f * h1);
            acc0 = fmaf(h0, sm.w2v[d],     acc0);
            acc1 = fmaf(h1, sm.w2v[d + 1], acc1);
        }
        float acc = acc0 + acc1;
        acc += __shfl_xor_sync(0xffffffffu, acc, 1);
        if (h == 0) out_value[(size_t)b * 256 + p] = acc;
    }
}

extern "C" void kernel_launch(void* const* d_in, const int* in_sizes, int n_in,
                              void* d_out, int out_size) {
    const float* states    = (const float*)d_in[0];
    const float* policies  = (const float*)d_in[1];
    const float* actions   = (const float*)d_in[2];
    const float* states_o  = (const float*)d_in[3];
    const float* actions_o = (const float*)d_in[4];
    const float* Wk  = (const float*)d_in[5];
    const float* Wq  = (const float*)d_in[6];
    const float* Wv  = (const float*)d_in[7];
    const float* Wko = (const float*)d_in[8];
    const float* Wqo = (const float*)d_in[9];
    const float* Wvo = (const float*)d_in[10];
    const float* W1  = (const float*)d_in[11];
    const float* W2  = (const float*)d_in[12];

    float* out       = (float*)d_out;
    float* out_value = out;                    // [B,N,N,1]
    float* out_w     = out + BB * 256;         // [B,N,N]
    float* out_wo    = out + 2 * BB * 256;     // [B,N,M,1]

    cudaFuncSetAttribute(critic_kernel,
                         cudaFuncAttributeMaxDynamicSharedMemorySize,
                         (int)sizeof(Smem));

    gg_kernel<<<32, 256>>>(Wq, Wk, Wqo, Wko);
    critic_kernel<<<BB, 512, sizeof(Smem)>>>(states, policies, actions,
                                             states_o, actions_o,
                                             Wv, Wvo, W1, W2,
                                             out_value, out_w, out_wo);
}

// round 13
// speedup vs baseline: 1.2103x; 1.0679x over previous
#include <cuda_runtime.h>

#define BB 128
typedef unsigned long long u64;

__device__ __forceinline__ u64 pack2(float x, float y){
    u64 r; asm("mov.b64 %0,{%1,%2};" : "=l"(r) : "f"(x), "f"(y)); return r;
}
__device__ __forceinline__ void unpack2(u64 a, float& x, float& y){
    asm("mov.b64 {%0,%1},%2;" : "=f"(x), "=f"(y) : "l"(a));
}
__device__ __forceinline__ u64 fma2(u64 a, u64 b, u64 c){
    u64 d; asm("fma.rn.f32x2 %0,%1,%2,%3;" : "=l"(d) : "l"(a), "l"(b), "l"(c)); return d;
}
__device__ __forceinline__ float fast_tanh(float x){
    float e = __expf(2.0f * x);
    return 1.0f - __fdividef(2.0f, e + 1.0f);
}

// Folded score matrices (recomputed every launch by gg_kernel -> deterministic)
__device__ float Gd [128 * 128];   // Wq  @ Wk^T
__device__ float God[128 * 128];   // Wqo @ Wko^T

// ============ Precompute kernel (verbatim from passing R10, + PDL trigger) ============
__global__ __launch_bounds__(256, 1)
void gg_kernel(const float* __restrict__ Wq,  const float* __restrict__ Wk,
               const float* __restrict__ Wqo, const float* __restrict__ Wko)
{
    // Let the dependent critic grid launch immediately; it only synchronizes
    // (cudaGridDependencySynchronize) before reading Gd/God, which waits for
    // THIS grid's completion with full memory visibility.
    cudaTriggerProgrammaticLaunchCompletion();

    __shared__ float aT[128 * 18];   // aT[a][r], 16 rows
    __shared__ float bT[128 * 66];   // bT[a][e], 64 e-cols
    const int tid = threadIdx.x;
    const int cta = blockIdx.x;          // 0..31
    const bool second = cta >= 16;
    const int c  = cta & 15;
    const int d0 = (c >> 1) * 16;
    const int e0 = (c & 1) * 64;
    const float* Wa = second ? Wqo : Wq;
    const float* Wb = second ? Wko : Wk;
    float* Gout = second ? God : Gd;

    for (int idx = tid; idx < 16 * 128; idx += 256) {
        int r = idx >> 7, a = idx & 127;
        aT[a * 18 + r] = Wa[(d0 + r) * 128 + a];
    }
    for (int idx = tid; idx < 64 * 128; idx += 256) {
        int e = idx >> 7, a = idx & 127;
        bT[a * 66 + e] = Wb[(e0 + e) * 128 + a];
    }
    __syncthreads();

    const int e2 = tid & 31;
    const int rg = tid >> 5;
    u64 acc0 = 0ull, acc1 = 0ull;
#pragma unroll 4
    for (int a = 0; a < 128; a++) {
        const u64 we = *reinterpret_cast<const u64*>(&bT[a * 66 + 2 * e2]);
        const float2 ar = *reinterpret_cast<const float2*>(&aT[a * 18 + 2 * rg]);
        acc0 = fma2(pack2(ar.x, ar.x), we, acc0);
        acc1 = fma2(pack2(ar.y, ar.y), we, acc1);
    }
    float x0, x1, y0, y1;
    unpack2(acc0, x0, x1);
    unpack2(acc1, y0, y1);
    float* g0 = Gout + (d0 + 2 * rg) * 128 + e0 + 2 * e2;
    *reinterpret_cast<float2*>(g0)       = make_float2(x0, x1);
    *reinterpret_cast<float2*>(g0 + 128) = make_float2(y0, y1);
}

#define ST_T16 20
#define ST_T32 36
#define ST_RM  132
#define ST_PX  66

struct Smem {
    float sT    [128 * ST_T16];
    float oaoT  [136 * ST_T32];
    float act   [16 * 8];
    float pol   [16 * 8];
    float YT    [128 * ST_T16];  // (s@G)^T
    float YoT   [128 * ST_T16];  // (s@Go)^T
    float t     [16 * ST_RM];
    float t1    [16 * ST_RM];
    float avoT  [128 * ST_T32];
    float avactT[128 * ST_T16];
    float deltaT[128 * ST_T16];
    float w     [256];
    float wo    [512];
    float P     [16 * ST_PX];
    float X     [32 * ST_PX];
    float u     [16 * ST_PX];
    float v     [16 * ST_PX];
    float w2v   [64];
};

__global__ __launch_bounds__(512, 1)
void critic_kernel(const float* __restrict__ states,
                   const float* __restrict__ policies,
                   const float* __restrict__ actions,
                   const float* __restrict__ states_o,
                   const float* __restrict__ actions_o,
                   const float* __restrict__ Wv,
                   const float* __restrict__ Wvo,
                   const float* __restrict__ W1,  const float* __restrict__ W2,
                   float* __restrict__ out_value,
                   float* __restrict__ out_w,
                   float* __restrict__ out_wo)
{
    extern __shared__ unsigned char smem_raw[];
    Smem& sm = *reinterpret_cast<Smem*>(smem_raw);

    const int b    = blockIdx.x;
    const int tid  = threadIdx.x;
    const int warp = tid >> 5;

    // ---------- Stage-1 config ----------
    // warps 0-3 : Y = s@G / Yo = s@Go (gated on gg grid via PDL gridsync)
    // warps 4-7 : Wv (k-split x col-split)
    // warps 8-15: Wvo (8-row x col-split, full 136k)
    int r0 = 0, kbeg, kend, koff, col;
    const float* Wm;
    int cls;  // 0: G/Go, 1: Wv, 2: Wvo
    if (warp < 4) {
        cls = 0;
        col = (warp & 1) * 64 + (tid & 31) * 2;
        kbeg = 0; kend = 128;
        koff = warp * 32;
        Wm = ((warp >> 1) == 0 ? Gd : God) + col;
    } else if (warp < 8) {
        cls = 1;
        const int sub = warp - 4;
        col = (sub & 1) * 64 + (tid & 31) * 2;
        const int kh = sub >> 1;
        kbeg = kh * 64; kend = kbeg + 64;
        koff = kbeg + ((sub * 16 + 8) & 63);
        Wm = Wv + col;
    } else {
        cls = 2;
        const int wrp = warp - 8;
        r0 = (wrp >> 1) * 8;
        col = (wrp & 1) * 64 + (tid & 31) * 2;
        kbeg = 0; kend = 136;
        koff = (wrp * 16 + 4) & 127;
        Wm = Wvo + col;
    }
    auto ldw = [&](int k){ return *reinterpret_cast<const float2*>(Wm + k * 128); };

    // ---------- Stage 0: load + transpose inputs ----------
    {
        const int k  = tid & 127;
        const int g  = tid >> 7;
        const int rr = g * 4;
        const float* S = states + (size_t)b * 16 * 128;
        {
            float a0 = S[(rr + 0) * 128 + k];
            float a1 = S[(rr + 1) * 128 + k];
            float a2 = S[(rr + 2) * 128 + k];
            float a3 = S[(rr + 3) * 128 + k];
            *reinterpret_cast<float4*>(&sm.sT[k * ST_T16 + rr]) = make_float4(a0, a1, a2, a3);
        }
        const float* SO = states_o + (size_t)b * 32 * 128;
#pragma unroll
        for (int h = 0; h < 32; h += 16) {
            float a0 = SO[(rr + h + 0) * 128 + k];
            float a1 = SO[(rr + h + 1) * 128 + k];
            float a2 = SO[(rr + h + 2) * 128 + k];
            float a3 = SO[(rr + h + 3) * 128 + k];
            *reinterpret_cast<float4*>(&sm.oaoT[k * ST_T32 + rr + h]) = make_float4(a0, a1, a2, a3);
        }
        if (tid < 256) {
            int kk8 = tid >> 5, m = tid & 31;
            sm.oaoT[(128 + kk8) * ST_T32 + m] = actions_o[(size_t)b * 32 * 8 + m * 8 + kk8];
        }
        if (tid < 128) {
            int r = tid >> 3, c = tid & 7;
            sm.act[r * 8 + c] = actions[(size_t)b * 16 * 8 + r * 8 + c];
            sm.pol[r * 8 + c] = policies[(size_t)b * 16 * 8 + r * 8 + c];
        }
        if (tid < 64) sm.w2v[tid] = W2[tid];
    }

    // Deep prefetch BEFORE the barrier — only for non-gated warps (Wv/Wvo)
    float2 wA, wB, wC, wD, wE, wF, wG, wH;
    if (cls != 0) {
        wA = ldw(koff + 0); wB = ldw(koff + 1); wC = ldw(koff + 2); wD = ldw(koff + 3);
        wE = ldw(koff + 4); wF = ldw(koff + 5); wG = ldw(koff + 6); wH = ldw(koff + 7);
    }

    __syncthreads();

    // Gate: warps 0-3 wait (HW PDL semantics) for the gg grid to fully complete
    // with memory visibility, then prefetch their G rows.
    if (cls == 0) {
        cudaGridDependencySynchronize();
        wA = ldw(koff + 0); wB = ldw(koff + 1); wC = ldw(koff + 2); wD = ldw(koff + 3);
        wE = ldw(koff + 4); wF = ldw(koff + 5); wG = ldw(koff + 6); wH = ldw(koff + 7);
    }

    // ---------- Stage 1 ----------
    if (cls < 2) {
        u64 acc[2][8];
#pragma unroll
        for (int j = 0; j < 2; j++)
#pragma unroll
            for (int p = 0; p < 8; p++) acc[j][p] = 0ull;

        auto step = [&](int k, float2 w2) {
            const float* Ak = sm.sT + k * ST_T16;
            const ulonglong2 A0 = *reinterpret_cast<const ulonglong2*>(Ak);
            const ulonglong2 A1 = *reinterpret_cast<const ulonglong2*>(Ak + 4);
            const ulonglong2 A2 = *reinterpret_cast<const ulonglong2*>(Ak + 8);
            const ulonglong2 A3 = *reinterpret_cast<const ulonglong2*>(Ak + 12);
            const u64 wp0 = pack2(w2.x, w2.x);
            const u64 wp1 = pack2(w2.y, w2.y);
            acc[0][0] = fma2(A0.x, wp0, acc[0][0]);
            acc[0][1] = fma2(A0.y, wp0, acc[0][1]);
            acc[0][2] = fma2(A1.x, wp0, acc[0][2]);
            acc[0][3] = fma2(A1.y, wp0, acc[0][3]);
            acc[0][4] = fma2(A2.x, wp0, acc[0][4]);
            acc[0][5] = fma2(A2.y, wp0, acc[0][5]);
            acc[0][6] = fma2(A3.x, wp0, acc[0][6]);
            acc[0][7] = fma2(A3.y, wp0, acc[0][7]);
            acc[1][0] = fma2(A0.x, wp1, acc[1][0]);
            acc[1][1] = fma2(A0.y, wp1, acc[1][1]);
            acc[1][2] = fma2(A1.x, wp1, acc[1][2]);
            acc[1][3] = fma2(A1.y, wp1, acc[1][3]);
            acc[1][4] = fma2(A2.x, wp1, acc[1][4]);
            acc[1][5] = fma2(A2.y, wp1, acc[1][5]);
            acc[1][6] = fma2(A3.x, wp1, acc[1][6]);
            acc[1][7] = fma2(A3.y, wp1, acc[1][7]);
        };

        step(koff + 0, wA);
        step(koff + 1, wB);
        step(koff + 2, wC);
        step(koff + 3, wD);
        step(koff + 4, wE);
        step(koff + 5, wF);
        step(koff + 6, wG);
        step(koff + 7, wH);
#pragma unroll 8
        for (int k = koff + 8; k < kend; k++) step(k, ldw(k));
#pragma unroll 8
        for (int k = kbeg; k < koff; k++) step(k, ldw(k));

        if (cls == 0) {
            float* oT = ((warp >> 1) == 0 ? sm.YT : sm.YoT);
#pragma unroll
            for (int j = 0; j < 2; j++) {
                float* d = oT + (col + j) * ST_T16;
                ulonglong2 s0 = {acc[j][0], acc[j][1]};
                ulonglong2 s1 = {acc[j][2], acc[j][3]};
                ulonglong2 s2 = {acc[j][4], acc[j][5]};
                ulonglong2 s3 = {acc[j][6], acc[j][7]};
                *reinterpret_cast<ulonglong2*>(d)      = s0;
                *reinterpret_cast<ulonglong2*>(d + 4)  = s1;
                *reinterpret_cast<ulonglong2*>(d + 8)  = s2;
                *reinterpret_cast<ulonglong2*>(d + 12) = s3;
            }
        } else {
            float* dt = ((warp - 4) >> 1) ? sm.t1 : sm.t;
#pragma unroll
            for (int p = 0; p < 8; p++) {
                float x0, y0, x1, y1;
                unpack2(acc[0][p], x0, y0);
                unpack2(acc[1][p], x1, y1);
                *reinterpret_cast<float2*>(&dt[(2 * p + 0) * ST_RM + col]) = make_float2(x0, x1);
                *reinterpret_cast<float2*>(&dt[(2 * p + 1) * ST_RM + col]) = make_float2(y0, y1);
            }
        }
    } else {
        // Wvo: 8 rows x 2 cols, 136 k-steps, tanh epilogue
        u64 acc[2][4];
#pragma unroll
        for (int j = 0; j < 2; j++)
#pragma unroll
            for (int p = 0; p < 4; p++) acc[j][p] = 0ull;

        auto stepo = [&](int k, float2 w2) {
            const float* Ak = sm.oaoT + k * ST_T32 + r0;
            const ulonglong2 A0 = *reinterpret_cast<const ulonglong2*>(Ak);
            const ulonglong2 A1 = *reinterpret_cast<const ulonglong2*>(Ak + 4);
            const u64 wp0 = pack2(w2.x, w2.x);
            const u64 wp1 = pack2(w2.y, w2.y);
            acc[0][0] = fma2(A0.x, wp0, acc[0][0]);
            acc[0][1] = fma2(A0.y, wp0, acc[0][1]);
            acc[0][2] = fma2(A1.x, wp0, acc[0][2]);
            acc[0][3] = fma2(A1.y, wp0, acc[0][3]);
            acc[1][0] = fma2(A0.x, wp1, acc[1][0]);
            acc[1][1] = fma2(A0.y, wp1, acc[1][1]);
            acc[1][2] = fma2(A1.x, wp1, acc[1][2]);
            acc[1][3] = fma2(A1.y, wp1, acc[1][3]);
        };

        stepo(koff + 0, wA);
        stepo(koff + 1, wB);
        stepo(koff + 2, wC);
        stepo(koff + 3, wD);
        stepo(koff + 4, wE);
        stepo(koff + 5, wF);
        stepo(koff + 6, wG);
        stepo(koff + 7, wH);
#pragma unroll 8
        for (int k = koff + 8; k < 136; k++) stepo(k, ldw(k));
#pragma unroll 8
        for (int k = 0; k < koff; k++) stepo(k, ldw(k));

#pragma unroll
        for (int j = 0; j < 2; j++) {
            float t0, t1_, t2, t3, t4, t5, t6, t7;
            unpack2(acc[j][0], t0, t1_);
            unpack2(acc[j][1], t2, t3);
            unpack2(acc[j][2], t4, t5);
            unpack2(acc[j][3], t6, t7);
            float* d = sm.avoT + (col + j) * ST_T32 + r0;
            *reinterpret_cast<float4*>(d)     = make_float4(fast_tanh(t0), fast_tanh(t1_), fast_tanh(t2), fast_tanh(t3));
            *reinterpret_cast<float4*>(d + 4) = make_float4(fast_tanh(t4), fast_tanh(t5), fast_tanh(t6), fast_tanh(t7));
        }
    }
    __syncthreads();

    // ---------- Stage 2: avactT/deltaT tails + attention scores ----------
    {
        const int g  = tid >> 7;
        const int c  = tid & 127;
        const int rr = g * 4;
        float aa[4], ap[4];
#pragma unroll
        for (int i = 0; i < 4; i++) {
            float tv = sm.t[(rr + i) * ST_RM + c] + sm.t1[(rr + i) * ST_RM + c];
            aa[i] = tv; ap[i] = tv;
        }
#pragma unroll
        for (int k = 0; k < 8; k++) {
            float wv = Wv[(128 + k) * 128 + c];
#pragma unroll
            for (int i = 0; i < 4; i++) {
                aa[i] = fmaf(sm.act[(rr + i) * 8 + k], wv, aa[i]);
                ap[i] = fmaf(sm.pol[(rr + i) * 8 + k], wv, ap[i]);
            }
        }
        float ta[4], dl[4];
#pragma unroll
        for (int i = 0; i < 4; i++) {
            ta[i] = fast_tanh(aa[i]);
            dl[i] = fast_tanh(ap[i]) - ta[i];
        }
        *reinterpret_cast<float4*>(&sm.avactT[c * ST_T16 + rr]) = make_float4(ta[0], ta[1], ta[2], ta[3]);
        *reinterpret_cast<float4*>(&sm.deltaT[c * ST_T16 + rr]) = make_float4(dl[0], dl[1], dl[2], dl[3]);
    }
    const float scale = 0.08838834764831845f;  // 1/sqrt(128)
    if (tid < 128) {
        const int i = tid >> 3, j2 = tid & 7;
        u64 a0 = 0ull, a1 = 0ull;
#pragma unroll 4
        for (int k = 0; k < 128; k += 2) {
            const float q0 = sm.YT[(k + 0) * ST_T16 + i];
            const float q1 = sm.YT[(k + 1) * ST_T16 + i];
            const u64 kp0 = *reinterpret_cast<const u64*>(&sm.sT[(k + 0) * ST_T16 + 2 * j2]);
            const u64 kp1 = *reinterpret_cast<const u64*>(&sm.sT[(k + 1) * ST_T16 + 2 * j2]);
            a0 = fma2(pack2(q0, q0), kp0, a0);
            a1 = fma2(pack2(q1, q1), kp1, a1);
        }
        float s0, s1, t0, t1;
        unpack2(a0, s0, s1);
        unpack2(a1, t0, t1);
        *reinterpret_cast<float2*>(&sm.w[i * 16 + 2 * j2]) =
            make_float2((s0 + t0) * scale, (s1 + t1) * scale);
    } else if (tid < 384) {
        const int t2 = tid - 128;
        const int i = t2 >> 4, m2 = t2 & 15;
        u64 a0 = 0ull, a1 = 0ull;
#pragma unroll 4
        for (int k = 0; k < 128; k += 2) {
            const float q0 = sm.YoT[(k + 0) * ST_T16 + i];
            const float q1 = sm.YoT[(k + 1) * ST_T16 + i];
            const u64 kp0 = *reinterpret_cast<const u64*>(&sm.oaoT[(k + 0) * ST_T32 + 2 * m2]);
            const u64 kp1 = *reinterpret_cast<const u64*>(&sm.oaoT[(k + 1) * ST_T32 + 2 * m2]);
            a0 = fma2(pack2(q0, q0), kp0, a0);
            a1 = fma2(pack2(q1, q1), kp1, a1);
        }
        float s0, s1, t0, t1;
        unpack2(a0, s0, s1);
        unpack2(a1, t0, t1);
        *reinterpret_cast<float2*>(&sm.wo[i * 32 + 2 * m2]) =
            make_float2((s0 + t0) * scale, (s1 + t1) * scale);
    }

    // ---------- Stage-3 config + deep prefetch (before barrier) ----------
    const float* AT;
    const float* Wg;
    float* dst3;
    int r03, strideA3, col3;
    if (tid < 256) {
        const int cq2 = tid & 31;
        const int rg  = tid >> 5;
        col3 = cq2 * 2;
        AT   = (rg < 4 ? sm.avactT : sm.deltaT);
        r03  = (rg & 3) * 4;
        strideA3 = ST_T16;
        Wg   = W1;
        dst3 = (rg < 4 ? sm.P : sm.v);
    } else {
        const int tid2 = tid - 256;
        const int cq2 = tid2 & 31;
        const int rg  = tid2 >> 5;
        col3 = cq2 * 2;
        AT   = sm.avoT;
        r03  = rg * 4;
        strideA3 = ST_T32;
        Wg   = W1 + 128 * 64;
        dst3 = sm.X;
    }
    const int koff3 = ((tid >> 5) & 7) * 16;
    auto ldw3 = [&](int k){ return *reinterpret_cast<const float2*>(Wg + k * 64 + col3); };
    float2 pA = ldw3(koff3 + 0), pB = ldw3(koff3 + 1), pC = ldw3(koff3 + 2), pD = ldw3(koff3 + 3);
    float2 pE = ldw3(koff3 + 4), pF = ldw3(koff3 + 5), pG = ldw3(koff3 + 6), pH = ldw3(koff3 + 7);

    __syncthreads();

    // ---------- Stage 3: softmaxes + P/v/X GEMMs ----------
    if (tid < 16) {
        const int i = tid;
        float mx = -1e30f;
#pragma unroll
        for (int j = 0; j < 16; j++) mx = fmaxf(mx, sm.w[i * 16 + j]);
        float s = 0.f, e[16];
#pragma unroll
        for (int j = 0; j < 16; j++) { e[j] = __expf(sm.w[i * 16 + j] - mx); s += e[j]; }
        const float inv = __fdividef(1.f, s);
#pragma unroll
        for (int j = 0; j < 16; j++) {
            float p = e[j] * inv;
            sm.w[i * 16 + j] = p;
            out_w[(size_t)b * 256 + i * 16 + j] = p;
        }
    } else if (tid < 48) {
        const int m = tid - 16;
        float mx = -1e30f;
#pragma unroll
        for (int i = 0; i < 16; i++) mx = fmaxf(mx, sm.wo[i * 32 + m]);
        float s = 0.f, e[16];
#pragma unroll
        for (int i = 0; i < 16; i++) { e[i] = __expf(sm.wo[i * 32 + m] - mx); s += e[i]; }
        const float inv = __fdividef(1.f, s);
#pragma unroll
        for (int i = 0; i < 16; i++) {
            float p = e[i] * inv;
            sm.wo[i * 32 + m] = p;
            out_wo[(size_t)b * 512 + i * 32 + m] = p;
        }
    }
    {
        u64 a00 = 0ull, a01 = 0ull, a10 = 0ull, a11 = 0ull;
        auto step3 = [&](int k, float2 wv) {
            const ulonglong2 A = *reinterpret_cast<const ulonglong2*>(&AT[k * strideA3 + r03]);
            const u64 wp0 = pack2(wv.x, wv.x);
            const u64 wp1 = pack2(wv.y, wv.y);
            a00 = fma2(A.x, wp0, a00);
            a01 = fma2(A.y, wp0, a01);
            a10 = fma2(A.x, wp1, a10);
            a11 = fma2(A.y, wp1, a11);
        };
        step3(koff3 + 0, pA);
        step3(koff3 + 1, pB);
        step3(koff3 + 2, pC);
        step3(koff3 + 3, pD);
        step3(koff3 + 4, pE);
        step3(koff3 + 5, pF);
        step3(koff3 + 6, pG);
        step3(koff3 + 7, pH);
#pragma unroll 8
        for (int k = koff3 + 8; k < 128; k++) step3(k, ldw3(k));
#pragma unroll 8
        for (int k = 0; k < koff3; k++) step3(k, ldw3(k));

        float x0, x1, x2, x3, y0, y1, y2, y3;
        unpack2(a00, x0, x1); unpack2(a01, x2, x3);
        unpack2(a10, y0, y1); unpack2(a11, y2, y3);
        *reinterpret_cast<float2*>(&dst3[(r03 + 0) * ST_PX + col3]) = make_float2(x0, y0);
        *reinterpret_cast<float2*>(&dst3[(r03 + 1) * ST_PX + col3]) = make_float2(x1, y1);
        *reinterpret_cast<float2*>(&dst3[(r03 + 2) * ST_PX + col3]) = make_float2(x2, y2);
        *reinterpret_cast<float2*>(&dst3[(r03 + 3) * ST_PX + col3]) = make_float2(x3, y3);
    }
    __syncthreads();

    // ---------- Stage 5: u = w @ P + wo @ X ----------
    {
        const int i = tid >> 5;
        const int c = (tid & 31) * 2;
        float acc0 = 0.f, acc1 = 0.f, bcc0 = 0.f, bcc1 = 0.f;
#pragma unroll
        for (int j = 0; j < 16; j += 2) {
            const float wv0 = sm.w[i * 16 + j];
            const float wv1 = sm.w[i * 16 + j + 1];
            const float2 p0 = *reinterpret_cast<const float2*>(&sm.P[j * ST_PX + c]);
            const float2 p1 = *reinterpret_cast<const float2*>(&sm.P[(j + 1) * ST_PX + c]);
            acc0 = fmaf(wv0, p0.x, acc0);
            acc1 = fmaf(wv0, p0.y, acc1);
            bcc0 = fmaf(wv1, p1.x, bcc0);
            bcc1 = fmaf(wv1, p1.y, bcc1);
        }
#pragma unroll
        for (int m = 0; m < 32; m += 2) {
            const float wv0 = sm.wo[i * 32 + m];
            const float wv1 = sm.wo[i * 32 + m + 1];
            const float2 x0 = *reinterpret_cast<const float2*>(&sm.X[m * ST_PX + c]);
            const float2 x1 = *reinterpret_cast<const float2*>(&sm.X[(m + 1) * ST_PX + c]);
            acc0 = fmaf(wv0, x0.x, acc0);
            acc1 = fmaf(wv0, x0.y, acc1);
            bcc0 = fmaf(wv1, x1.x, bcc0);
            bcc1 = fmaf(wv1, x1.y, bcc1);
        }
        *reinterpret_cast<float2*>(&sm.u[i * ST_PX + c]) = make_float2(acc0 + bcc0, acc1 + bcc1);
    }
    __syncthreads();

    // ---------- Stage 6: final value ----------
    {
        const int p = tid >> 1, h = tid & 1;
        const int i = p >> 4, j = p & 15;
        const float wt = sm.w[i * 16 + j];
        float acc0 = 0.f, acc1 = 0.f;
        const int d0 = h * 32;
#pragma unroll
        for (int d = d0; d < d0 + 32; d += 2) {
            float h0 = fmaf(wt, sm.v[j * ST_PX + d],     sm.u[i * ST_PX + d]);
            float h1 = fmaf(wt, sm.v[j * ST_PX + d + 1], sm.u[i * ST_PX + d + 1]);
            h0 = fmaxf(h0, 0.01f * h0);
            h1 = fmaxf(h1, 0.01f * h1);
            acc0 = fmaf(h0, sm.w2v[d],     acc0);
            acc1 = fmaf(h1, sm.w2v[d + 1], acc1);
        }
        float acc = acc0 + acc1;
        acc += __shfl_xor_sync(0xffffffffu, acc, 1);
        if (h == 0) out_value[(size_t)b * 256 + p] = acc;
    }
}

extern "C" void kernel_launch(void* const* d_in, const int* in_sizes, int n_in,
                              void* d_out, int out_size) {
    const float* states    = (const float*)d_in[0];
    const float* policies  = (const float*)d_in[1];
    const float* actions   = (const float*)d_in[2];
    const float* states_o  = (const float*)d_in[3];
    const float* actions_o = (const float*)d_in[4];
    const float* Wk  = (const float*)d_in[5];
    const float* Wq  = (const float*)d_in[6];
    const float* Wv  = (const float*)d_in[7];
    const float* Wko = (const float*)d_in[8];
    const float* Wqo = (const float*)d_in[9];
    const float* Wvo = (const float*)d_in[10];
    const float* W1  = (const float*)d_in[11];
    const float* W2  = (const float*)d_in[12];

    float* out       = (float*)d_out;
    float* out_value = out;                    // [B,N,N,1]
    float* out_w     = out + BB * 256;         // [B,N,N]
    float* out_wo    = out + 2 * BB * 256;     // [B,N,M,1]

    cudaFuncSetAttribute(critic_kernel,
                         cudaFuncAttributeMaxDynamicSharedMemorySize,
                         (int)sizeof(Smem));

    // Primary: gg (triggers dependent launch immediately at its start)
    gg_kernel<<<32, 256>>>(Wq, Wk, Wqo, Wko);

    // Secondary: critic, launched with programmatic dependent launch so its
    // prologue (input loads, Wv/Wvo GEMM prefetch) overlaps gg; warps 0-3
    // gridsync before reading Gd/God.
    cudaLaunchConfig_t cfg = {};
    cfg.gridDim = dim3(BB, 1, 1);
    cfg.blockDim = dim3(512, 1, 1);
    cfg.dynamicSmemBytes = sizeof(Smem);
    cudaLaunchAttribute attrs[1];
    attrs[0].id = cudaLaunchAttributeProgrammaticStreamSerialization;
    attrs[0].val.programmaticStreamSerializationAllowed = 1;
    cfg.attrs = attrs;
    cfg.numAttrs = 1;

    cudaLaunchKernelEx(&cfg, critic_kernel,
                       states, policies, actions, states_o, actions_o,
                       Wv, Wvo, W1, W2, out_value, out_w, out_wo);
}

// round 14
// speedup vs baseline: 1.2130x; 1.0022x over previous
#include <cuda_runtime.h>

#define BB 128
typedef unsigned long long u64;

__device__ __forceinline__ u64 pack2(float x, float y){
    u64 r; asm("mov.b64 %0,{%1,%2};" : "=l"(r) : "f"(x), "f"(y)); return r;
}
__device__ __forceinline__ void unpack2(u64 a, float& x, float& y){
    asm("mov.b64 {%0,%1},%2;" : "=f"(x), "=f"(y) : "l"(a));
}
__device__ __forceinline__ u64 fma2(u64 a, u64 b, u64 c){
    u64 d; asm("fma.rn.f32x2 %0,%1,%2,%3;" : "=l"(d) : "l"(a), "l"(b), "l"(c)); return d;
}
__device__ __forceinline__ float fast_tanh(float x){
    float e = __expf(2.0f * x);
    return 1.0f - __fdividef(2.0f, e + 1.0f);
}

// Folded score matrices (recomputed every launch by gg_kernel -> deterministic)
__device__ float Gd [128 * 128];   // Wq  @ Wk^T
__device__ float God[128 * 128];   // Wqo @ Wko^T

// ============ Precompute kernel: 16 CTAs x 512 threads (single-wave fit) ============
// Each CTA computes a 16-row x 128-col tile. Thread-half 0 runs the PROVEN R10
// per-thread loop on cols 0-63 (bTa); thread-half 1 the same loop on cols 64-127 (bTb).
#define GG_AT   (128 * 18)
#define GG_BT   (128 * 66)
#define GG_SMEM ((GG_AT + 2 * GG_BT) * sizeof(float))

__global__ __launch_bounds__(512, 1)
void gg_kernel(const float* __restrict__ Wq,  const float* __restrict__ Wk,
               const float* __restrict__ Wqo, const float* __restrict__ Wko)
{
    // Let the dependent critic grid launch immediately; it gridsyncs before
    // reading Gd/God.
    cudaTriggerProgrammaticLaunchCompletion();

    extern __shared__ float gg_sm[];
    float* aT  = gg_sm;                 // [128][18]  : 16 rows of Wa, transposed
    float* bTa = gg_sm + GG_AT;         // [128][66]  : cols 0-63 of Wb, transposed
    float* bTb = bTa + GG_BT;           // [128][66]  : cols 64-127

    const int tid = threadIdx.x;
    const int cta = blockIdx.x;          // 0..15
    const bool second = cta >= 8;
    const int d0 = (cta & 7) * 16;
    const float* Wa = second ? Wqo : Wq;
    const float* Wb = second ? Wko : Wk;
    float* Gout = second ? God : Gd;

    for (int idx = tid; idx < 16 * 128; idx += 512) {
        int r = idx >> 7, a = idx & 127;
        aT[a * 18 + r] = Wa[(d0 + r) * 128 + a];
    }
    for (int idx = tid; idx < 64 * 128; idx += 512) {
        int e = idx >> 7, a = idx & 127;
        bTa[a * 66 + e] = Wb[e * 128 + a];
        bTb[a * 66 + e] = Wb[(64 + e) * 128 + a];
    }
    __syncthreads();

    // R10-verbatim per-thread compute, selected per thread-half
    const int half = tid >> 8;          // 0 or 1
    const int t2   = tid & 255;
    const int e2 = t2 & 31;             // e-pair within the 64-col half
    const int rg = t2 >> 5;             // row-pair 0..7
    const float* bT = half ? bTb : bTa;
    const int e0 = half * 64;

    u64 acc0 = 0ull, acc1 = 0ull;
#pragma unroll 4
    for (int a = 0; a < 128; a++) {
        const u64 we = *reinterpret_cast<const u64*>(&bT[a * 66 + 2 * e2]);
        const float2 ar = *reinterpret_cast<const float2*>(&aT[a * 18 + 2 * rg]);
        acc0 = fma2(pack2(ar.x, ar.x), we, acc0);
        acc1 = fma2(pack2(ar.y, ar.y), we, acc1);
    }
    float x0, x1, y0, y1;
    unpack2(acc0, x0, x1);
    unpack2(acc1, y0, y1);
    float* g0 = Gout + (d0 + 2 * rg) * 128 + e0 + 2 * e2;
    *reinterpret_cast<float2*>(g0)       = make_float2(x0, x1);
    *reinterpret_cast<float2*>(g0 + 128) = make_float2(y0, y1);
}

#define ST_T16 20
#define ST_T32 36
#define ST_RM  132
#define ST_PX  66

struct Smem {
    float sT    [128 * ST_T16];
    float oaoT  [136 * ST_T32];
    float act   [16 * 8];
    float pol   [16 * 8];
    float YT    [128 * ST_T16];  // (s@G)^T
    float YoT   [128 * ST_T16];  // (s@Go)^T
    float t     [16 * ST_RM];
    float t1    [16 * ST_RM];
    float avoT  [128 * ST_T32];
    float avactT[128 * ST_T16];
    float deltaT[128 * ST_T16];
    float w     [256];
    float wo    [512];
    float P     [16 * ST_PX];
    float X     [32 * ST_PX];
    float u     [16 * ST_PX];
    float v     [16 * ST_PX];
    float w2v   [64];
};

__global__ __launch_bounds__(512, 1)
void critic_kernel(const float* __restrict__ states,
                   const float* __restrict__ policies,
                   const float* __restrict__ actions,
                   const float* __restrict__ states_o,
                   const float* __restrict__ actions_o,
                   const float* __restrict__ Wv,
                   const float* __restrict__ Wvo,
                   const float* __restrict__ W1,  const float* __restrict__ W2,
                   float* __restrict__ out_value,
                   float* __restrict__ out_w,
                   float* __restrict__ out_wo)
{
    extern __shared__ unsigned char smem_raw[];
    Smem& sm = *reinterpret_cast<Smem*>(smem_raw);

    const int b    = blockIdx.x;
    const int tid  = threadIdx.x;
    const int warp = tid >> 5;

    // ---------- Stage-1 config ----------
    // warps 0-3 : Y = s@G / Yo = s@Go (gated on gg grid via PDL gridsync)
    // warps 4-7 : Wv (k-split x col-split)
    // warps 8-15: Wvo (8-row x col-split, full 136k)
    int r0 = 0, kbeg, kend, koff, col;
    const float* Wm;
    int cls;  // 0: G/Go, 1: Wv, 2: Wvo
    if (warp < 4) {
        cls = 0;
        col = (warp & 1) * 64 + (tid & 31) * 2;
        kbeg = 0; kend = 128;
        koff = warp * 32;
        Wm = ((warp >> 1) == 0 ? Gd : God) + col;
    } else if (warp < 8) {
        cls = 1;
        const int sub = warp - 4;
        col = (sub & 1) * 64 + (tid & 31) * 2;
        const int kh = sub >> 1;
        kbeg = kh * 64; kend = kbeg + 64;
        koff = kbeg + ((sub * 16 + 8) & 63);
        Wm = Wv + col;
    } else {
        cls = 2;
        const int wrp = warp - 8;
        r0 = (wrp >> 1) * 8;
        col = (wrp & 1) * 64 + (tid & 31) * 2;
        kbeg = 0; kend = 136;
        koff = (wrp * 16 + 4) & 127;
        Wm = Wvo + col;
    }
    auto ldw = [&](int k){ return *reinterpret_cast<const float2*>(Wm + k * 128); };

    // ---------- Stage 0: load + transpose inputs ----------
    {
        const int k  = tid & 127;
        const int g  = tid >> 7;
        const int rr = g * 4;
        const float* S = states + (size_t)b * 16 * 128;
        {
            float a0 = S[(rr + 0) * 128 + k];
            float a1 = S[(rr + 1) * 128 + k];
            float a2 = S[(rr + 2) * 128 + k];
            float a3 = S[(rr + 3) * 128 + k];
            *reinterpret_cast<float4*>(&sm.sT[k * ST_T16 + rr]) = make_float4(a0, a1, a2, a3);
        }
        const float* SO = states_o + (size_t)b * 32 * 128;
#pragma unroll
        for (int h = 0; h < 32; h += 16) {
            float a0 = SO[(rr + h + 0) * 128 + k];
            float a1 = SO[(rr + h + 1) * 128 + k];
            float a2 = SO[(rr + h + 2) * 128 + k];
            float a3 = SO[(rr + h + 3) * 128 + k];
            *reinterpret_cast<float4*>(&sm.oaoT[k * ST_T32 + rr + h]) = make_float4(a0, a1, a2, a3);
        }
        if (tid < 256) {
            int kk8 = tid >> 5, m = tid & 31;
            sm.oaoT[(128 + kk8) * ST_T32 + m] = actions_o[(size_t)b * 32 * 8 + m * 8 + kk8];
        }
        if (tid < 128) {
            int r = tid >> 3, c = tid & 7;
            sm.act[r * 8 + c] = actions[(size_t)b * 16 * 8 + r * 8 + c];
            sm.pol[r * 8 + c] = policies[(size_t)b * 16 * 8 + r * 8 + c];
        }
        if (tid < 64) sm.w2v[tid] = W2[tid];
    }

    // Deep prefetch BEFORE the barrier — only for non-gated warps (Wv/Wvo)
    float2 wA, wB, wC, wD, wE, wF, wG, wH;
    if (cls != 0) {
        wA = ldw(koff + 0); wB = ldw(koff + 1); wC = ldw(koff + 2); wD = ldw(koff + 3);
        wE = ldw(koff + 4); wF = ldw(koff + 5); wG = ldw(koff + 6); wH = ldw(koff + 7);
    }

    __syncthreads();

    // Gate: warps 0-3 wait (HW PDL semantics) for the gg grid to fully complete
    // with memory visibility, then prefetch their G rows.
    if (cls == 0) {
        cudaGridDependencySynchronize();
        wA = ldw(koff + 0); wB = ldw(koff + 1); wC = ldw(koff + 2); wD = ldw(koff + 3);
        wE = ldw(koff + 4); wF = ldw(koff + 5); wG = ldw(koff + 6); wH = ldw(koff + 7);
    }

    // ---------- Stage 1 ----------
    if (cls < 2) {
        u64 acc[2][8];
#pragma unroll
        for (int j = 0; j < 2; j++)
#pragma unroll
            for (int p = 0; p < 8; p++) acc[j][p] = 0ull;

        auto step = [&](int k, float2 w2) {
            const float* Ak = sm.sT + k * ST_T16;
            const ulonglong2 A0 = *reinterpret_cast<const ulonglong2*>(Ak);
            const ulonglong2 A1 = *reinterpret_cast<const ulonglong2*>(Ak + 4);
            const ulonglong2 A2 = *reinterpret_cast<const ulonglong2*>(Ak + 8);
            const ulonglong2 A3 = *reinterpret_cast<const ulonglong2*>(Ak + 12);
            const u64 wp0 = pack2(w2.x, w2.x);
            const u64 wp1 = pack2(w2.y, w2.y);
            acc[0][0] = fma2(A0.x, wp0, acc[0][0]);
            acc[0][1] = fma2(A0.y, wp0, acc[0][1]);
            acc[0][2] = fma2(A1.x, wp0, acc[0][2]);
            acc[0][3] = fma2(A1.y, wp0, acc[0][3]);
            acc[0][4] = fma2(A2.x, wp0, acc[0][4]);
            acc[0][5] = fma2(A2.y, wp0, acc[0][5]);
            acc[0][6] = fma2(A3.x, wp0, acc[0][6]);
            acc[0][7] = fma2(A3.y, wp0, acc[0][7]);
            acc[1][0] = fma2(A0.x, wp1, acc[1][0]);
            acc[1][1] = fma2(A0.y, wp1, acc[1][1]);
            acc[1][2] = fma2(A1.x, wp1, acc[1][2]);
            acc[1][3] = fma2(A1.y, wp1, acc[1][3]);
            acc[1][4] = fma2(A2.x, wp1, acc[1][4]);
            acc[1][5] = fma2(A2.y, wp1, acc[1][5]);
            acc[1][6] = fma2(A3.x, wp1, acc[1][6]);
            acc[1][7] = fma2(A3.y, wp1, acc[1][7]);
        };

        step(koff + 0, wA);
        step(koff + 1, wB);
        step(koff + 2, wC);
        step(koff + 3, wD);
        step(koff + 4, wE);
        step(koff + 5, wF);
        step(koff + 6, wG);
        step(koff + 7, wH);
#pragma unroll 8
        for (int k = koff + 8; k < kend; k++) step(k, ldw(k));
#pragma unroll 8
        for (int k = kbeg; k < koff; k++) step(k, ldw(k));

        if (cls == 0) {
            float* oT = ((warp >> 1) == 0 ? sm.YT : sm.YoT);
#pragma unroll
            for (int j = 0; j < 2; j++) {
                float* d = oT + (col + j) * ST_T16;
                ulonglong2 s0 = {acc[j][0], acc[j][1]};
                ulonglong2 s1 = {acc[j][2], acc[j][3]};
                ulonglong2 s2 = {acc[j][4], acc[j][5]};
                ulonglong2 s3 = {acc[j][6], acc[j][7]};
                *reinterpret_cast<ulonglong2*>(d)      = s0;
                *reinterpret_cast<ulonglong2*>(d + 4)  = s1;
                *reinterpret_cast<ulonglong2*>(d + 8)  = s2;
                *reinterpret_cast<ulonglong2*>(d + 12) = s3;
            }
        } else {
            float* dt = ((warp - 4) >> 1) ? sm.t1 : sm.t;
#pragma unroll
            for (int p = 0; p < 8; p++) {
                float x0, y0, x1, y1;
                unpack2(acc[0][p], x0, y0);
                unpack2(acc[1][p], x1, y1);
                *reinterpret_cast<float2*>(&dt[(2 * p + 0) * ST_RM + col]) = make_float2(x0, x1);
                *reinterpret_cast<float2*>(&dt[(2 * p + 1) * ST_RM + col]) = make_float2(y0, y1);
            }
        }
    } else {
        // Wvo: 8 rows x 2 cols, 136 k-steps, tanh epilogue
        u64 acc[2][4];
#pragma unroll
        for (int j = 0; j < 2; j++)
#pragma unroll
            for (int p = 0; p < 4; p++) acc[j][p] = 0ull;

        auto stepo = [&](int k, float2 w2) {
            const float* Ak = sm.oaoT + k * ST_T32 + r0;
            const ulonglong2 A0 = *reinterpret_cast<const ulonglong2*>(Ak);
            const ulonglong2 A1 = *reinterpret_cast<const ulonglong2*>(Ak + 4);
            const u64 wp0 = pack2(w2.x, w2.x);
            const u64 wp1 = pack2(w2.y, w2.y);
            acc[0][0] = fma2(A0.x, wp0, acc[0][0]);
            acc[0][1] = fma2(A0.y, wp0, acc[0][1]);
            acc[0][2] = fma2(A1.x, wp0, acc[0][2]);
            acc[0][3] = fma2(A1.y, wp0, acc[0][3]);
            acc[1][0] = fma2(A0.x, wp1, acc[1][0]);
            acc[1][1] = fma2(A0.y, wp1, acc[1][1]);
            acc[1][2] = fma2(A1.x, wp1, acc[1][2]);
            acc[1][3] = fma2(A1.y, wp1, acc[1][3]);
        };

        stepo(koff + 0, wA);
        stepo(koff + 1, wB);
        stepo(koff + 2, wC);
        stepo(koff + 3, wD);
        stepo(koff + 4, wE);
        stepo(koff + 5, wF);
        stepo(koff + 6, wG);
        stepo(koff + 7, wH);
#pragma unroll 8
        for (int k = koff + 8; k < 136; k++) stepo(k, ldw(k));
#pragma unroll 8
        for (int k = 0; k < koff; k++) stepo(k, ldw(k));

#pragma unroll
        for (int j = 0; j < 2; j++) {
            float t0, t1_, t2, t3, t4, t5, t6, t7;
            unpack2(acc[j][0], t0, t1_);
            unpack2(acc[j][1], t2, t3);
            unpack2(acc[j][2], t4, t5);
            unpack2(acc[j][3], t6, t7);
            float* d = sm.avoT + (col + j) * ST_T32 + r0;
            *reinterpret_cast<float4*>(d)     = make_float4(fast_tanh(t0), fast_tanh(t1_), fast_tanh(t2), fast_tanh(t3));
            *reinterpret_cast<float4*>(d + 4) = make_float4(fast_tanh(t4), fast_tanh(t5), fast_tanh(t6), fast_tanh(t7));
        }
    }
    __syncthreads();

    // ---------- Stage 2: avactT/deltaT tails + attention scores ----------
    {
        const int g  = tid >> 7;
        const int c  = tid & 127;
        const int rr = g * 4;
        float aa[4], ap[4];
#pragma unroll
        for (int i = 0; i < 4; i++) {
            float tv = sm.t[(rr + i) * ST_RM + c] + sm.t1[(rr + i) * ST_RM + c];
            aa[i] = tv; ap[i] = tv;
        }
#pragma unroll
        for (int k = 0; k < 8; k++) {
            float wv = Wv[(128 + k) * 128 + c];
#pragma unroll
            for (int i = 0; i < 4; i++) {
                aa[i] = fmaf(sm.act[(rr + i) * 8 + k], wv, aa[i]);
                ap[i] = fmaf(sm.pol[(rr + i) * 8 + k], wv, ap[i]);
            }
        }
        float ta[4], dl[4];
#pragma unroll
        for (int i = 0; i < 4; i++) {
            ta[i] = fast_tanh(aa[i]);
            dl[i] = fast_tanh(ap[i]) - ta[i];
        }
        *reinterpret_cast<float4*>(&sm.avactT[c * ST_T16 + rr]) = make_float4(ta[0], ta[1], ta[2], ta[3]);
        *reinterpret_cast<float4*>(&sm.deltaT[c * ST_T16 + rr]) = make_float4(dl[0], dl[1], dl[2], dl[3]);
    }
    const float scale = 0.08838834764831845f;  // 1/sqrt(128)
    if (tid < 128) {
        const int i = tid >> 3, j2 = tid & 7;
        u64 a0 = 0ull, a1 = 0ull;
#pragma unroll 4
        for (int k = 0; k < 128; k += 2) {
            const float q0 = sm.YT[(k + 0) * ST_T16 + i];
            const float q1 = sm.YT[(k + 1) * ST_T16 + i];
            const u64 kp0 = *reinterpret_cast<const u64*>(&sm.sT[(k + 0) * ST_T16 + 2 * j2]);
            const u64 kp1 = *reinterpret_cast<const u64*>(&sm.sT[(k + 1) * ST_T16 + 2 * j2]);
            a0 = fma2(pack2(q0, q0), kp0, a0);
            a1 = fma2(pack2(q1, q1), kp1, a1);
        }
        float s0, s1, t0, t1;
        unpack2(a0, s0, s1);
        unpack2(a1, t0, t1);
        *reinterpret_cast<float2*>(&sm.w[i * 16 + 2 * j2]) =
            make_float2((s0 + t0) * scale, (s1 + t1) * scale);
    } else if (tid < 384) {
        const int t2 = tid - 128;
        const int i = t2 >> 4, m2 = t2 & 15;
        u64 a0 = 0ull, a1 = 0ull;
#pragma unroll 4
        for (int k = 0; k < 128; k += 2) {
            const float q0 = sm.YoT[(k + 0) * ST_T16 + i];
            const float q1 = sm.YoT[(k + 1) * ST_T16 + i];
            const u64 kp0 = *reinterpret_cast<const u64*>(&sm.oaoT[(k + 0) * ST_T32 + 2 * m2]);
            const u64 kp1 = *reinterpret_cast<const u64*>(&sm.oaoT[(k + 1) * ST_T32 + 2 * m2]);
            a0 = fma2(pack2(q0, q0), kp0, a0);
            a1 = fma2(pack2(q1, q1), kp1, a1);
        }
        float s0, s1, t0, t1;
        unpack2(a0, s0, s1);
        unpack2(a1, t0, t1);
        *reinterpret_cast<float2*>(&sm.wo[i * 32 + 2 * m2]) =
            make_float2((s0 + t0) * scale, (s1 + t1) * scale);
    }

    // ---------- Stage-3 config + deep prefetch (before barrier) ----------
    const float* AT;
    const float* Wg;
    float* dst3;
    int r03, strideA3, col3;
    if (tid < 256) {
        const int cq2 = tid & 31;
        const int rg  = tid >> 5;
        col3 = cq2 * 2;
        AT   = (rg < 4 ? sm.avactT : sm.deltaT);
        r03  = (rg & 3) * 4;
        strideA3 = ST_T16;
        Wg   = W1;
        dst3 = (rg < 4 ? sm.P : sm.v);
    } else {
        const int tid2 = tid - 256;
        const int cq2 = tid2 & 31;
        const int rg  = tid2 >> 5;
        col3 = cq2 * 2;
        AT   = sm.avoT;
        r03  = rg * 4;
        strideA3 = ST_T32;
        Wg   = W1 + 128 * 64;
        dst3 = sm.X;
    }
    const int koff3 = ((tid >> 5) & 7) * 16;
    auto ldw3 = [&](int k){ return *reinterpret_cast<const float2*>(Wg + k * 64 + col3); };
    float2 pA = ldw3(koff3 + 0), pB = ldw3(koff3 + 1), pC = ldw3(koff3 + 2), pD = ldw3(koff3 + 3);
    float2 pE = ldw3(koff3 + 4), pF = ldw3(koff3 + 5), pG = ldw3(koff3 + 6), pH = ldw3(koff3 + 7);

    __syncthreads();

    // ---------- Stage 3: softmaxes + P/v/X GEMMs ----------
    if (tid < 16) {
        const int i = tid;
        float mx = -1e30f;
#pragma unroll
        for (int j = 0; j < 16; j++) mx = fmaxf(mx, sm.w[i * 16 + j]);
        float s = 0.f, e[16];
#pragma unroll
        for (int j = 0; j < 16; j++) { e[j] = __expf(sm.w[i * 16 + j] - mx); s += e[j]; }
        const float inv = __fdividef(1.f, s);
#pragma unroll
        for (int j = 0; j < 16; j++) {
            float p = e[j] * inv;
            sm.w[i * 16 + j] = p;
            out_w[(size_t)b * 256 + i * 16 + j] = p;
        }
    } else if (tid < 48) {
        const int m = tid - 16;
        float mx = -1e30f;
#pragma unroll
        for (int i = 0; i < 16; i++) mx = fmaxf(mx, sm.wo[i * 32 + m]);
        float s = 0.f, e[16];
#pragma unroll
        for (int i = 0; i < 16; i++) { e[i] = __expf(sm.wo[i * 32 + m] - mx); s += e[i]; }
        const float inv = __fdividef(1.f, s);
#pragma unroll
        for (int i = 0; i < 16; i++) {
            float p = e[i] * inv;
            sm.wo[i * 32 + m] = p;
            out_wo[(size_t)b * 512 + i * 32 + m] = p;
        }
    }
    {
        u64 a00 = 0ull, a01 = 0ull, a10 = 0ull, a11 = 0ull;
        auto step3 = [&](int k, float2 wv) {
            const ulonglong2 A = *reinterpret_cast<const ulonglong2*>(&AT[k * strideA3 + r03]);
            const u64 wp0 = pack2(wv.x, wv.x);
            const u64 wp1 = pack2(wv.y, wv.y);
            a00 = fma2(A.x, wp0, a00);
            a01 = fma2(A.y, wp0, a01);
            a10 = fma2(A.x, wp1, a10);
            a11 = fma2(A.y, wp1, a11);
        };
        step3(koff3 + 0, pA);
        step3(koff3 + 1, pB);
        step3(koff3 + 2, pC);
        step3(koff3 + 3, pD);
        step3(koff3 + 4, pE);
        step3(koff3 + 5, pF);
        step3(koff3 + 6, pG);
        step3(koff3 + 7, pH);
#pragma unroll 8
        for (int k = koff3 + 8; k < 128; k++) step3(k, ldw3(k));
#pragma unroll 8
        for (int k = 0; k < koff3; k++) step3(k, ldw3(k));

        float x0, x1, x2, x3, y0, y1, y2, y3;
        unpack2(a00, x0, x1); unpack2(a01, x2, x3);
        unpack2(a10, y0, y1); unpack2(a11, y2, y3);
        *reinterpret_cast<float2*>(&dst3[(r03 + 0) * ST_PX + col3]) = make_float2(x0, y0);
        *reinterpret_cast<float2*>(&dst3[(r03 + 1) * ST_PX + col3]) = make_float2(x1, y1);
        *reinterpret_cast<float2*>(&dst3[(r03 + 2) * ST_PX + col3]) = make_float2(x2, y2);
        *reinterpret_cast<float2*>(&dst3[(r03 + 3) * ST_PX + col3]) = make_float2(x3, y3);
    }
    __syncthreads();

    // ---------- Stage 5: u = w @ P + wo @ X ----------
    {
        const int i = tid >> 5;
        const int c = (tid & 31) * 2;
        float acc0 = 0.f, acc1 = 0.f, bcc0 = 0.f, bcc1 = 0.f;
#pragma unroll
        for (int j = 0; j < 16; j += 2) {
            const float wv0 = sm.w[i * 16 + j];
            const float wv1 = sm.w[i * 16 + j + 1];
            const float2 p0 = *reinterpret_cast<const float2*>(&sm.P[j * ST_PX + c]);
            const float2 p1 = *reinterpret_cast<const float2*>(&sm.P[(j + 1) * ST_PX + c]);
            acc0 = fmaf(wv0, p0.x, acc0);
            acc1 = fmaf(wv0, p0.y, acc1);
            bcc0 = fmaf(wv1, p1.x, bcc0);
            bcc1 = fmaf(wv1, p1.y, bcc1);
        }
#pragma unroll
        for (int m = 0; m < 32; m += 2) {
            const float wv0 = sm.wo[i * 32 + m];
            const float wv1 = sm.wo[i * 32 + m + 1];
            const float2 x0 = *reinterpret_cast<const float2*>(&sm.X[m * ST_PX + c]);
            const float2 x1 = *reinterpret_cast<const float2*>(&sm.X[(m + 1) * ST_PX + c]);
            acc0 = fmaf(wv0, x0.x, acc0);
            acc1 = fmaf(wv0, x0.y, acc1);
            bcc0 = fmaf(wv1, x1.x, bcc0);
            bcc1 = fmaf(wv1, x1.y, bcc1);
        }
        *reinterpret_cast<float2*>(&sm.u[i * ST_PX + c]) = make_float2(acc0 + bcc0, acc1 + bcc1);
    }
    __syncthreads();

    // ---------- Stage 6: final value ----------
    {
        const int p = tid >> 1, h = tid & 1;
        const int i = p >> 4, j = p & 15;
        const float wt = sm.w[i * 16 + j];
        float acc0 = 0.f, acc1 = 0.f;
        const int d0 = h * 32;
#pragma unroll
        for (int d = d0; d < d0 + 32; d += 2) {
            float h0 = fmaf(wt, sm.v[j * ST_PX + d],     sm.u[i * ST_PX + d]);
            float h1 = fmaf(wt, sm.v[j * ST_PX + d + 1], sm.u[i * ST_PX + d + 1]);
            h0 = fmaxf(h0, 0.01f * h0);
            h1 = fmaxf(h1, 0.01f * h1);
            acc0 = fmaf(h0, sm.w2v[d],     acc0);
            acc1 = fmaf(h1, sm.w2v[d + 1], acc1);
        }
        float acc = acc0 + acc1;
        acc += __shfl_xor_sync(0xffffffffu, acc, 1);
        if (h == 0) out_value[(size_t)b * 256 + p] = acc;
    }
}

extern "C" void kernel_launch(void* const* d_in, const int* in_sizes, int n_in,
                              void* d_out, int out_size) {
    const float* states    = (const float*)d_in[0];
    const float* policies  = (const float*)d_in[1];
    const float* actions   = (const float*)d_in[2];
    const float* states_o  = (const float*)d_in[3];
    const float* actions_o = (const float*)d_in[4];
    const float* Wk  = (const float*)d_in[5];
    const float* Wq  = (const float*)d_in[6];
    const float* Wv  = (const float*)d_in[7];
    const float* Wko = (const float*)d_in[8];
    const float* Wqo = (const float*)d_in[9];
    const float* Wvo = (const float*)d_in[10];
    const float* W1  = (const float*)d_in[11];
    const float* W2  = (const float*)d_in[12];

    float* out       = (float*)d_out;
    float* out_value = out;                    // [B,N,N,1]
    float* out_w     = out + BB * 256;         // [B,N,N]
    float* out_wo    = out + 2 * BB * 256;     // [B,N,M,1]

    cudaFuncSetAttribute(critic_kernel,
                         cudaFuncAttributeMaxDynamicSharedMemorySize,
                         (int)sizeof(Smem));
    cudaFuncSetAttribute(gg_kernel,
                         cudaFuncAttributeMaxDynamicSharedMemorySize,
                         (int)GG_SMEM);

    // Primary: gg (16 CTAs -> 16 + 128 = 144 <= 148 SMs, single co-resident wave).
    // Triggers dependent launch immediately at its start.
    gg_kernel<<<16, 512, GG_SMEM>>>(Wq, Wk, Wqo, Wko);

    // Secondary: critic with programmatic dependent launch; prologue overlaps gg,
    // warps 0-3 gridsync before reading Gd/God.
    cudaLaunchConfig_t cfg = {};
    cfg.gridDim = dim3(BB, 1, 1);
    cfg.blockDim = dim3(512, 1, 1);
    cfg.dynamicSmemBytes = sizeof(Smem);
    cudaLaunchAttribute attrs[1];
    attrs[0].id = cudaLaunchAttributeProgrammaticStreamSerialization;
    attrs[0].val.programmaticStreamSerializationAllowed = 1;
    cfg.attrs = attrs;
    cfg.numAttrs = 1;

    cudaLaunchKernelEx(&cfg, critic_kernel,
                       states, policies, actions, states_o, actions_o,
                       Wv, Wvo, W1, W2, out_value, out_w, out_wo);
}